// round 8
// baseline (speedup 1.0000x reference)
#include <cuda_runtime.h>
#include <math.h>
#include <stdint.h>

#define BATCH 4096
#define K1 8450
#define K2 1250
#define KP1P 8704          // h1 row pitch (17 * 512)
#define KP2P 1536          // h2 row pitch (3 * 512)

// ---------------- scratch (device globals; zero-initialized) ---------------
__device__ float g_h1[(size_t)BATCH * KP1P];
__device__ float g_h2[(size_t)BATCH * KP2P];
__device__ float g_f3[BATCH * 50];
__device__ float g_o2[BATCH * 10];
__device__ int   g_e1[BATCH];
__device__ int   g_e2[BATCH];
__device__ float g_W1[12 * KP1P];    // rows 0-9: l2c1@l1c1; 10-11: d1_w
__device__ float g_W2[12 * KP2P];
__device__ float g_b1c[12];
__device__ float g_b2c[12];
__device__ float g_part1[BATCH * 24];  // [b][split(2)][12]
__device__ float2 g_wpk1[50 * 9];      // conv1 weights duplicated (w,w)
__device__ float2 g_wpk2[50 * 450];    // conv2 weights ic-major [ic][oc][9], dup

// ================= merged prep kernel =======================================
__device__ void combine_part(
    const float* __restrict__ l1, const float* __restrict__ b1,
    const float* __restrict__ l2, const float* __restrict__ b2,
    const float* __restrict__ dw, const float* __restrict__ db,
    int K, int Kp, float* __restrict__ W12, float* __restrict__ bc12,
    int blk, float* l2T)
{
    int tid = threadIdx.x;
    for (int i = tid; i < 5000; i += 256) {
        int j = i / 500, r = i - j * 500;
        l2T[r * 12 + j] = l2[i];
    }
    for (int r = tid; r < 500; r += 256) { l2T[r * 12 + 10] = 0.f; l2T[r * 12 + 11] = 0.f; }
    __syncthreads();

    int k = blk * 256 + tid;
    if (k < Kp) {
        if (k < K) {
            float acc[10];
            #pragma unroll
            for (int j = 0; j < 10; j++) acc[j] = 0.f;
            for (int r = 0; r < 500; r++) {
                float a = __ldg(&l1[(size_t)r * K + k]);
                float4 w0 = *(const float4*)&l2T[r * 12];
                float4 w1 = *(const float4*)&l2T[r * 12 + 4];
                float2 w2 = *(const float2*)&l2T[r * 12 + 8];
                acc[0] += a * w0.x; acc[1] += a * w0.y; acc[2] += a * w0.z; acc[3] += a * w0.w;
                acc[4] += a * w1.x; acc[5] += a * w1.y; acc[6] += a * w1.z; acc[7] += a * w1.w;
                acc[8] += a * w2.x; acc[9] += a * w2.y;
            }
            #pragma unroll
            for (int j = 0; j < 10; j++) W12[(size_t)j * Kp + k] = acc[j];
            W12[(size_t)10 * Kp + k] = __ldg(&dw[k]);
            W12[(size_t)11 * Kp + k] = __ldg(&dw[K + k]);
        } else {
            #pragma unroll
            for (int j = 0; j < 12; j++) W12[(size_t)j * Kp + k] = 0.f;
        }
    }
    if (blk == 0) {
        if (tid < 10) {
            float a = b2[tid];
            for (int r = 0; r < 500; r++) a += l2[tid * 500 + r] * b1[r];
            bc12[tid] = a;
        } else if (tid < 12) {
            bc12[tid] = db[tid - 10];
        }
    }
}

__global__ __launch_bounds__(256) void prep_kernel(
    const float* l1c1_w, const float* l1c1_b, const float* l2c1_w, const float* l2c1_b,
    const float* l1c2_w, const float* l1c2_b, const float* l2c2_w, const float* l2c2_b,
    const float* d1_w, const float* d1_b, const float* d2_w, const float* d2_b,
    const float* c1_w, const float* c2_w,
    float* W1, float* b1c, float* W2, float* b2c, float2* wpk1, float2* wpk2)
{
    __shared__ __align__(16) float l2T[500 * 12];
    int bx = blockIdx.x, tid = threadIdx.x;
    if (bx < 34) {
        combine_part(l1c1_w, l1c1_b, l2c1_w, l2c1_b, d1_w, d1_b, K1, KP1P, W1, b1c, bx, l2T);
    } else if (bx < 40) {
        combine_part(l1c2_w, l1c2_b, l2c2_w, l2c2_b, d2_w, d2_b, K2, KP2P, W2, b2c, bx - 34, l2T);
    } else if (bx == 40) {
        for (int i = tid; i < 450; i += 256) { float v = c1_w[i]; wpk1[i] = make_float2(v, v); }
    } else {
        int i = (bx - 41) * 256 + tid;
        if (i < 22500) {
            int oc = i / 450, r = i - oc * 450;
            int ic = r / 9, k = r - ic * 9;
            float v = c2_w[i];
            wpk2[ic * 450 + oc * 9 + k] = make_float2(v, v);
        }
    }
}

// ---------------- conv1: register patch + packed f32x2 ----------------------
__global__ __launch_bounds__(192) void conv1_kernel(
    const float* __restrict__ x, const float2* __restrict__ wpk,
    const float* __restrict__ bias, float* __restrict__ h1)
{
    int b = blockIdx.x;
    __shared__ __align__(16) float xs[784];
    __shared__ __align__(16) float2 ws[450];
    __shared__ __align__(16) float bs[50];
    int tid = threadIdx.x;
    {
        const float4* xb = (const float4*)(x + (size_t)b * 784);
        for (int i = tid; i < 196; i += 192) ((float4*)xs)[i] = xb[i];
        for (int i = tid; i < 450; i += 192) ws[i] = wpk[i];
        for (int i = tid; i < 50;  i += 192) bs[i] = bias[i];
    }
    __syncthreads();
    if (tid >= 169) return;

    const int py = tid / 13, px = tid % 13;
    const int Y = 2 * py, X = 2 * px;
    float p[4][4];
    #pragma unroll
    for (int r = 0; r < 4; r++)
        #pragma unroll
        for (int c = 0; c < 4; c++) p[r][c] = xs[(Y + r) * 28 + X + c];
    unsigned long long P[4][3];
    #pragma unroll
    for (int r = 0; r < 4; r++)
        #pragma unroll
        for (int k = 0; k < 3; k++)
            asm("mov.b64 %0, {%1, %2};" : "=l"(P[r][k])
                : "r"(__float_as_uint(p[r][k])), "r"(__float_as_uint(p[r][k + 1])));

    float* hb = h1 + (size_t)b * KP1P + tid;
    for (int oc = 0; oc < 50; oc++) {
        unsigned long long aT = 0ULL, aB = 0ULL;
        #pragma unroll
        for (int ky = 0; ky < 3; ky++)
            #pragma unroll
            for (int kx = 0; kx < 3; kx++) {
                unsigned long long w2 = *(const unsigned long long*)&ws[oc * 9 + ky * 3 + kx];
                asm("fma.rn.f32x2 %0, %1, %2, %0;" : "+l"(aT) : "l"(P[ky][kx]), "l"(w2));
                asm("fma.rn.f32x2 %0, %1, %2, %0;" : "+l"(aB) : "l"(P[ky + 1][kx]), "l"(w2));
            }
        unsigned int u0, u1, u2, u3;
        asm("mov.b64 {%0, %1}, %2;" : "=r"(u0), "=r"(u1) : "l"(aT));
        asm("mov.b64 {%0, %1}, %2;" : "=r"(u2), "=r"(u3) : "l"(aB));
        float m = fmaxf(fmaxf(__uint_as_float(u0), __uint_as_float(u1)),
                        fmaxf(__uint_as_float(u2), __uint_as_float(u3)));
        m += bs[oc];
        hb[oc * 169] = fmaxf(m, 0.f);
    }
}

// ====== stagehead common tile sizes =========================================
#define SH_G 16
#define SH_CK 512
#define SH_SMEM ((12 * SH_CK + SH_G * SH_CK) * 4)   // 56 KB

// ---- split-K partial variant (stage 1): writes part[b*24 + split*12 + j] ---
__global__ __launch_bounds__(256) void stagehead_part_kernel(
    const float* __restrict__ f, int Kp,
    const float* __restrict__ W12, float* __restrict__ part)
{
    extern __shared__ __align__(16) float sh[];
    float* ws = sh;
    float* hs = sh + 12 * SH_CK;
    const int tid = threadIdx.x, lane = tid & 31, wid = tid >> 5;
    const int b0 = blockIdx.x * SH_G;
    const int split = blockIdx.y;
    const int s0 = wid * 2, s1 = s0 + 1;

    const int nch = Kp / SH_CK;
    const int half = (nch + 1) / 2;
    const int c0 = split * half;
    const int cE = min(nch, c0 + half);

    float acc0[12], acc1[12];
    #pragma unroll
    for (int j = 0; j < 12; j++) { acc0[j] = 0.f; acc1[j] = 0.f; }

    for (int c = c0; c < cE; c++) {
        const int kc = c * SH_CK;
        for (int i = tid; i < 12 * 128; i += 256) {
            int j = i >> 7, k4 = (i & 127) * 4;
            *(float4*)&ws[j * SH_CK + k4] = *(const float4*)&W12[(size_t)j * Kp + kc + k4];
        }
        for (int i = tid; i < SH_G * 128; i += 256) {
            int s = i >> 7, k4 = (i & 127) * 4;
            *(float4*)&hs[s * SH_CK + k4] = *(const float4*)&f[(size_t)(b0 + s) * Kp + kc + k4];
        }
        __syncthreads();

        #pragma unroll
        for (int it = 0; it < 4; it++) {
            const int kk = it * 128 + lane * 4;
            float4 f0 = *(float4*)&hs[s0 * SH_CK + kk];
            float4 f1 = *(float4*)&hs[s1 * SH_CK + kk];
            #pragma unroll
            for (int j = 0; j < 12; j++) {
                float4 w = *(float4*)&ws[j * SH_CK + kk];
                acc0[j] = fmaf(f0.x, w.x, fmaf(f0.y, w.y, fmaf(f0.z, w.z, fmaf(f0.w, w.w, acc0[j]))));
                acc1[j] = fmaf(f1.x, w.x, fmaf(f1.y, w.y, fmaf(f1.z, w.z, fmaf(f1.w, w.w, acc1[j]))));
            }
        }
        __syncthreads();
    }

    #pragma unroll
    for (int j = 0; j < 12; j++) {
        #pragma unroll
        for (int off = 16; off; off >>= 1) {
            acc0[j] += __shfl_xor_sync(0xffffffffu, acc0[j], off);
            acc1[j] += __shfl_xor_sync(0xffffffffu, acc1[j], off);
        }
    }
    if (lane == 0) {
        int ba = b0 + s0, bb = b0 + s1;
        #pragma unroll
        for (int j = 0; j < 12; j++) {
            part[ba * 24 + split * 12 + j] = acc0[j];
            part[bb * 24 + split * 12 + j] = acc1[j];
        }
    }
}

// ---- direct variant (stage 2): writes o (10) and exit flag -----------------
__global__ __launch_bounds__(256) void stagehead_kernel(
    const float* __restrict__ f, int Kp,
    const float* __restrict__ W12, const float* __restrict__ bc12,
    float* __restrict__ o, int* __restrict__ e)
{
    extern __shared__ __align__(16) float sh[];
    float* ws = sh;
    float* hs = sh + 12 * SH_CK;
    const int tid = threadIdx.x, lane = tid & 31, wid = tid >> 5;
    const int b0 = blockIdx.x * SH_G;
    const int s0 = wid * 2, s1 = s0 + 1;

    float acc0[12], acc1[12];
    #pragma unroll
    for (int j = 0; j < 12; j++) { acc0[j] = 0.f; acc1[j] = 0.f; }

    const int nchunks = Kp / SH_CK;
    for (int c = 0; c < nchunks; c++) {
        const int kc = c * SH_CK;
        for (int i = tid; i < 12 * 128; i += 256) {
            int j = i >> 7, k4 = (i & 127) * 4;
            *(float4*)&ws[j * SH_CK + k4] = *(const float4*)&W12[(size_t)j * Kp + kc + k4];
        }
        for (int i = tid; i < SH_G * 128; i += 256) {
            int s = i >> 7, k4 = (i & 127) * 4;
            *(float4*)&hs[s * SH_CK + k4] = *(const float4*)&f[(size_t)(b0 + s) * Kp + kc + k4];
        }
        __syncthreads();

        #pragma unroll
        for (int it = 0; it < 4; it++) {
            const int kk = it * 128 + lane * 4;
            float4 f0 = *(float4*)&hs[s0 * SH_CK + kk];
            float4 f1 = *(float4*)&hs[s1 * SH_CK + kk];
            #pragma unroll
            for (int j = 0; j < 12; j++) {
                float4 w = *(float4*)&ws[j * SH_CK + kk];
                acc0[j] = fmaf(f0.x, w.x, fmaf(f0.y, w.y, fmaf(f0.z, w.z, fmaf(f0.w, w.w, acc0[j]))));
                acc1[j] = fmaf(f1.x, w.x, fmaf(f1.y, w.y, fmaf(f1.z, w.z, fmaf(f1.w, w.w, acc1[j]))));
            }
        }
        __syncthreads();
    }

    #pragma unroll
    for (int j = 0; j < 12; j++) {
        #pragma unroll
        for (int off = 16; off; off >>= 1) {
            acc0[j] += __shfl_xor_sync(0xffffffffu, acc0[j], off);
            acc1[j] += __shfl_xor_sync(0xffffffffu, acc1[j], off);
        }
    }
    if (lane == 0) {
        int ba = b0 + s0, bb = b0 + s1;
        #pragma unroll
        for (int j = 0; j < 10; j++) {
            o[ba * 10 + j] = acc0[j] + bc12[j];
            o[bb * 10 + j] = acc1[j] + bc12[j];
        }
        e[ba] = (acc0[10] + bc12[10] >= acc0[11] + bc12[11]) ? 1 : 0;
        e[bb] = (acc1[10] + bc12[10] >= acc1[11] + bc12[11]) ? 1 : 0;
    }
}

// ---------------- conv2: derives e1 from partials, then conv ----------------
__global__ __launch_bounds__(256) void conv2_kernel(
    const float* __restrict__ h1, const float2* __restrict__ wpk,
    const float* __restrict__ bias, float* __restrict__ h2,
    const float* __restrict__ part, const float* __restrict__ b1c,
    int* __restrict__ e1)
{
    int b = blockIdx.x;
    __shared__ __align__(16) float hs[8450];
    __shared__ __align__(16) float2 wb[2][450];
    __shared__ __align__(16) float bss[50];
    __shared__ int sflag;
    const int tid = threadIdx.x;
    if (tid == 0) {
        float m0 = part[b * 24 + 10] + part[b * 24 + 22] + __ldg(&b1c[10]);
        float m1 = part[b * 24 + 11] + part[b * 24 + 23] + __ldg(&b1c[11]);
        int fl = (m0 >= m1) ? 1 : 0;
        e1[b] = fl;
        sflag = fl;
    }
    __syncthreads();
    if (sflag) return;

    {
        const float2* hb = (const float2*)(h1 + (size_t)b * KP1P);
        for (int i = tid; i < 4225; i += 256) ((float2*)hs)[i] = hb[i];
        for (int i = tid; i < 450; i += 256) wb[0][i] = wpk[i];
        for (int i = tid; i < 50;  i += 256) bss[i] = bias[i];
    }
    __syncthreads();

    const int osub = tid / 25, pos = tid % 25;
    const int oc0 = osub * 5;
    const int py = pos / 5, px = pos % 5;
    const int Y = 2 * py, X = 2 * px;
    const bool active = (tid < 250);

    unsigned long long aT[5], aB[5];
    #pragma unroll
    for (int j = 0; j < 5; j++) { aT[j] = 0ULL; aB[j] = 0ULL; }

    for (int ic = 0; ic < 50; ic++) {
        const int cur = ic & 1;
        if (ic + 1 < 50) {
            for (int i = tid; i < 450; i += 256)
                wb[cur ^ 1][i] = wpk[(ic + 1) * 450 + i];
        }
        if (active) {
            const float* hc = hs + ic * 169;
            float p[4][4];
            #pragma unroll
            for (int r = 0; r < 4; r++)
                #pragma unroll
                for (int c = 0; c < 4; c++) p[r][c] = hc[(Y + r) * 13 + X + c];
            unsigned long long P[4][3];
            #pragma unroll
            for (int r = 0; r < 4; r++)
                #pragma unroll
                for (int k = 0; k < 3; k++)
                    asm("mov.b64 %0, {%1, %2};" : "=l"(P[r][k])
                        : "r"(__float_as_uint(p[r][k])), "r"(__float_as_uint(p[r][k + 1])));
            #pragma unroll
            for (int ky = 0; ky < 3; ky++)
                #pragma unroll
                for (int kx = 0; kx < 3; kx++) {
                    const int wi = ky * 3 + kx;
                    #pragma unroll
                    for (int j = 0; j < 5; j++) {
                        unsigned long long w2 =
                            *(const unsigned long long*)&wb[cur][(oc0 + j) * 9 + wi];
                        asm("fma.rn.f32x2 %0, %1, %2, %0;" : "+l"(aT[j]) : "l"(P[ky][kx]), "l"(w2));
                        asm("fma.rn.f32x2 %0, %1, %2, %0;" : "+l"(aB[j]) : "l"(P[ky + 1][kx]), "l"(w2));
                    }
                }
        }
        __syncthreads();
    }

    if (active) {
        #pragma unroll
        for (int j = 0; j < 5; j++) {
            unsigned int u0, u1, u2, u3;
            asm("mov.b64 {%0, %1}, %2;" : "=r"(u0), "=r"(u1) : "l"(aT[j]));
            asm("mov.b64 {%0, %1}, %2;" : "=r"(u2), "=r"(u3) : "l"(aB[j]));
            float m = fmaxf(fmaxf(__uint_as_float(u0), __uint_as_float(u1)),
                            fmaxf(__uint_as_float(u2), __uint_as_float(u3)));
            m += bss[oc0 + j];
            h2[(size_t)b * KP2P + (oc0 + j) * 25 + pos] = fmaxf(m, 0.f);
        }
    }
}

// ---------------- conv3 (skips samples exiting at 1 or 2) -------------------
__global__ void conv3_kernel(const float* __restrict__ h2,
                             const float* __restrict__ w,
                             const float* __restrict__ bias,
                             float* __restrict__ f3,
                             const int* __restrict__ e1,
                             const int* __restrict__ e2)
{
    int b = blockIdx.x;
    if (e1[b] || e2[b]) return;
    __shared__ __align__(16) float hs[1250];
    const float* hb = h2 + (size_t)b * KP2P;
    for (int i = threadIdx.x; i < 1250; i += blockDim.x) hs[i] = hb[i];
    __syncthreads();

    int oc = threadIdx.x;
    if (oc >= 50) return;
    float a0 = 0.f, a1 = 0.f, a2 = 0.f, a3 = 0.f;
    for (int ic = 0; ic < 50; ic++) {
        const float* hc = hs + ic * 25;
        #pragma unroll
        for (int ky = 0; ky < 3; ky++)
            #pragma unroll
            for (int kx = 0; kx < 3; kx++) {
                float wv = __ldg(&w[oc * 450 + ic * 9 + ky * 3 + kx]);
                a0 += hc[ky * 5 + kx] * wv;
                a1 += hc[ky * 5 + kx + 1] * wv;
                a2 += hc[(ky + 1) * 5 + kx] * wv;
                a3 += hc[(ky + 1) * 5 + kx + 1] * wv;
            }
    }
    float m = fmaxf(fmaxf(a0, a1), fmaxf(a2, a3)) + __ldg(&bias[oc]);
    f3[b * 50 + oc] = fmaxf(m, 0.f);
}

// ==== stage3 + final fused: o3 in smem, then select + log_softmax ===========
#define S3_G 32
#define S3_SMEM ((25000 + 5000 + 500 + S3_G * 50 + S3_G * 500 + S3_G * 10) * 4)

__global__ __launch_bounds__(256) void stage3final_kernel(
    const float* __restrict__ f3,
    const float* __restrict__ l1w, const float* __restrict__ l1b,
    const float* __restrict__ l2w, const float* __restrict__ l2b,
    const int* __restrict__ e1, const int* __restrict__ e2,
    const float* __restrict__ part, const float* __restrict__ b1c,
    const float* __restrict__ o2, float* __restrict__ out)
{
    extern __shared__ __align__(16) float sm[];
    float* w1  = sm;                       // 25000
    float* w2  = sm + 25000;               // 5000
    float* b1  = sm + 30000;               // 500
    float* fs  = sm + 30500;               // 1600
    float* hid = sm + 32100;               // 16000
    float* o3s = sm + 48100;               // 320
    int tid = threadIdx.x;
    int b0 = blockIdx.x * S3_G;

    for (int i = tid; i < 25000; i += 256) w1[i] = l1w[i];
    for (int i = tid; i < 5000;  i += 256) w2[i] = l2w[i];
    for (int i = tid; i < 500;   i += 256) b1[i] = l1b[i];
    for (int i = tid; i < S3_G * 50; i += 256) fs[i] = f3[b0 * 50 + i];
    __syncthreads();

    for (int hh = tid; hh < S3_G * 500; hh += 256) {
        int s = hh / 500, j = hh - s * 500;
        float a = b1[j];
        const float* fr = fs + s * 50;
        const float* wr = w1 + j * 50;
        #pragma unroll 10
        for (int k = 0; k < 50; k++) a += fr[k] * wr[k];
        hid[hh] = fmaxf(a, 0.f);
    }
    __syncthreads();

    for (int oo = tid; oo < S3_G * 10; oo += 256) {
        int s = oo / 10, n = oo - s * 10;
        float a = __ldg(&l2b[n]);
        const float* hr = hid + s * 500;
        const float* wr = w2 + n * 500;
        #pragma unroll 4
        for (int j = 0; j < 500; j++) a += hr[j] * wr[j];
        o3s[s * 10 + n] = a;
    }
    __syncthreads();

    if (tid < S3_G) {
        int b = b0 + tid;
        float v[10];
        if (e1[b]) {
            #pragma unroll
            for (int j = 0; j < 10; j++)
                v[j] = part[b * 24 + j] + part[b * 24 + 12 + j] + __ldg(&b1c[j]);
        } else if (e2[b]) {
            #pragma unroll
            for (int j = 0; j < 10; j++) v[j] = o2[b * 10 + j];
        } else {
            #pragma unroll
            for (int j = 0; j < 10; j++) v[j] = o3s[tid * 10 + j];
        }
        float mx = -1e30f;
        #pragma unroll
        for (int j = 0; j < 10; j++) mx = fmaxf(mx, v[j]);
        float sum = 0.f;
        #pragma unroll
        for (int j = 0; j < 10; j++) sum += expf(v[j] - mx);
        float l = logf(sum);
        #pragma unroll
        for (int j = 0; j < 10; j++) out[b * 10 + j] = v[j] - mx - l;
    }
}

// ---------------- launch ----------------------------------------------------
extern "C" void kernel_launch(void* const* d_in, const int* in_sizes, int n_in,
                              void* d_out, int out_size)
{
    const float* x      = (const float*)d_in[0];
    const float* c1_w   = (const float*)d_in[1];
    const float* c1_b   = (const float*)d_in[2];
    const float* c2_w   = (const float*)d_in[3];
    const float* c2_b   = (const float*)d_in[4];
    const float* c3_w   = (const float*)d_in[5];
    const float* c3_b   = (const float*)d_in[6];
    const float* l1c1_w = (const float*)d_in[7];
    const float* l1c1_b = (const float*)d_in[8];
    const float* l2c1_w = (const float*)d_in[9];
    const float* l2c1_b = (const float*)d_in[10];
    const float* l1c2_w = (const float*)d_in[11];
    const float* l1c2_b = (const float*)d_in[12];
    const float* l2c2_w = (const float*)d_in[13];
    const float* l2c2_b = (const float*)d_in[14];
    const float* l1_w   = (const float*)d_in[15];
    const float* l1_b   = (const float*)d_in[16];
    const float* l2_w   = (const float*)d_in[17];
    const float* l2_b   = (const float*)d_in[18];
    const float* d1_w   = (const float*)d_in[19];
    const float* d1_b   = (const float*)d_in[20];
    const float* d2_w   = (const float*)d_in[21];
    const float* d2_b   = (const float*)d_in[22];
    float* out = (float*)d_out;

    float *h1, *h2, *f3, *o2, *W1, *W2, *b1c, *b2c, *part1;
    float2 *wpk1, *wpk2;
    int *e1, *e2;
    cudaGetSymbolAddress((void**)&h1,   g_h1);
    cudaGetSymbolAddress((void**)&h2,   g_h2);
    cudaGetSymbolAddress((void**)&f3,   g_f3);
    cudaGetSymbolAddress((void**)&o2,   g_o2);
    cudaGetSymbolAddress((void**)&e1,   g_e1);
    cudaGetSymbolAddress((void**)&e2,   g_e2);
    cudaGetSymbolAddress((void**)&W1,   g_W1);
    cudaGetSymbolAddress((void**)&W2,   g_W2);
    cudaGetSymbolAddress((void**)&b1c,  g_b1c);
    cudaGetSymbolAddress((void**)&b2c,  g_b2c);
    cudaGetSymbolAddress((void**)&part1, g_part1);
    cudaGetSymbolAddress((void**)&wpk1, g_wpk1);
    cudaGetSymbolAddress((void**)&wpk2, g_wpk2);

    static int attr_set = 0;
    if (!attr_set) {
        cudaFuncSetAttribute(stagehead_part_kernel,
                             cudaFuncAttributeMaxDynamicSharedMemorySize, SH_SMEM);
        cudaFuncSetAttribute(stagehead_kernel,
                             cudaFuncAttributeMaxDynamicSharedMemorySize, SH_SMEM);
        cudaFuncSetAttribute(stage3final_kernel,
                             cudaFuncAttributeMaxDynamicSharedMemorySize, S3_SMEM);
        attr_set = 1;
    }

    // prep (combine heads + pack conv weights), one launch
    prep_kernel<<<129, 256>>>(l1c1_w, l1c1_b, l2c1_w, l2c1_b,
                              l1c2_w, l1c2_b, l2c2_w, l2c2_b,
                              d1_w, d1_b, d2_w, d2_b, c1_w, c2_w,
                              W1, b1c, W2, b2c, wpk1, wpk2);

    // stage 1
    conv1_kernel<<<BATCH, 192>>>(x, wpk1, c1_b, h1);
    stagehead_part_kernel<<<dim3(BATCH / SH_G, 2), 256, SH_SMEM>>>(h1, KP1P, W1, part1);

    // stage 2 (conv2 derives e1 from partials)
    conv2_kernel<<<BATCH, 256>>>(h1, wpk2, c2_b, h2, part1, b1c, e1);
    stagehead_kernel<<<BATCH / SH_G, 256, SH_SMEM>>>(h2, KP2P, W2, b2c, o2, e2);

    // stage 3 + final select/log_softmax
    conv3_kernel<<<BATCH, 64>>>(h2, c3_w, c3_b, f3, e1, e2);
    stage3final_kernel<<<BATCH / S3_G, 256, S3_SMEM>>>(
        f3, l1_w, l1_b, l2_w, l2_b, e1, e2, part1, b1c, o2, out);
}

// round 9
// speedup vs baseline: 1.1696x; 1.1696x over previous
#include <cuda_runtime.h>
#include <math.h>
#include <stdint.h>

#define BATCH 4096
#define K1 8450
#define K2 1250
#define KP1P 8704          // h1 row pitch (17 * 512)
#define KP2P 1536          // h2 row pitch (3 * 512)

// ---------------- scratch (device globals; zero-initialized) ---------------
__device__ float g_h1[(size_t)BATCH * KP1P];
__device__ float g_h2[(size_t)BATCH * KP2P];
__device__ float g_f3[BATCH * 50];
__device__ float g_o2[BATCH * 10];
__device__ int   g_e1[BATCH];
__device__ int   g_e2[BATCH];
__device__ float g_W1[12 * KP1P];    // rows 0-9: l2c1@l1c1; 10-11: d1_w
__device__ float g_W2[12 * KP2P];
__device__ float g_b1c[12];
__device__ float g_b2c[12];
__device__ float g_part1[BATCH * 24];  // [b][split(2)][12]
__device__ float2 g_wpk2[50 * 500];    // conv2 weights [ic][oc][10] dup, pad k=9 zero

// ================= merged prep kernel =======================================
__device__ void combine_part(
    const float* __restrict__ l1, const float* __restrict__ b1,
    const float* __restrict__ l2, const float* __restrict__ b2,
    const float* __restrict__ dw, const float* __restrict__ db,
    int K, int Kp, float* __restrict__ W12, float* __restrict__ bc12,
    int blk, float* l2T)
{
    int tid = threadIdx.x;
    for (int i = tid; i < 5000; i += 256) {
        int j = i / 500, r = i - j * 500;
        l2T[r * 12 + j] = l2[i];
    }
    for (int r = tid; r < 500; r += 256) { l2T[r * 12 + 10] = 0.f; l2T[r * 12 + 11] = 0.f; }
    __syncthreads();

    int k = blk * 256 + tid;
    if (k < Kp) {
        if (k < K) {
            float acc[10];
            #pragma unroll
            for (int j = 0; j < 10; j++) acc[j] = 0.f;
            for (int r = 0; r < 500; r++) {
                float a = __ldg(&l1[(size_t)r * K + k]);
                float4 w0 = *(const float4*)&l2T[r * 12];
                float4 w1 = *(const float4*)&l2T[r * 12 + 4];
                float2 w2 = *(const float2*)&l2T[r * 12 + 8];
                acc[0] += a * w0.x; acc[1] += a * w0.y; acc[2] += a * w0.z; acc[3] += a * w0.w;
                acc[4] += a * w1.x; acc[5] += a * w1.y; acc[6] += a * w1.z; acc[7] += a * w1.w;
                acc[8] += a * w2.x; acc[9] += a * w2.y;
            }
            #pragma unroll
            for (int j = 0; j < 10; j++) W12[(size_t)j * Kp + k] = acc[j];
            W12[(size_t)10 * Kp + k] = __ldg(&dw[k]);
            W12[(size_t)11 * Kp + k] = __ldg(&dw[K + k]);
        } else {
            #pragma unroll
            for (int j = 0; j < 12; j++) W12[(size_t)j * Kp + k] = 0.f;
        }
    }
    if (blk == 0) {
        if (tid < 10) {
            float a = b2[tid];
            for (int r = 0; r < 500; r++) a += l2[tid * 500 + r] * b1[r];
            bc12[tid] = a;
        } else if (tid < 12) {
            bc12[tid] = db[tid - 10];
        }
    }
}

__global__ __launch_bounds__(256) void prep_kernel(
    const float* l1c1_w, const float* l1c1_b, const float* l2c1_w, const float* l2c1_b,
    const float* l1c2_w, const float* l1c2_b, const float* l2c2_w, const float* l2c2_b,
    const float* d1_w, const float* d1_b, const float* d2_w, const float* d2_b,
    const float* c2_w,
    float* W1, float* b1c, float* W2, float* b2c, float2* wpk2)
{
    __shared__ __align__(16) float l2T[500 * 12];
    int bx = blockIdx.x, tid = threadIdx.x;
    if (bx < 34) {
        combine_part(l1c1_w, l1c1_b, l2c1_w, l2c1_b, d1_w, d1_b, K1, KP1P, W1, b1c, bx, l2T);
    } else if (bx < 40) {
        combine_part(l1c2_w, l1c2_b, l2c2_w, l2c2_b, d2_w, d2_b, K2, KP2P, W2, b2c, bx - 34, l2T);
    } else {
        int i = (bx - 40) * 256 + tid;
        if (i < 22500) {
            int oc = i / 450, r = i - oc * 450;
            int ic = r / 9, k = r - ic * 9;
            float v = c2_w[i];
            wpk2[ic * 500 + oc * 10 + k] = make_float2(v, v);   // pad k=9 stays zero
        }
    }
}

// ---------------- conv1: register patch + packed f32x2 ----------------------
// packs its own weights (no prep dependency)
__global__ __launch_bounds__(192) void conv1_kernel(
    const float* __restrict__ x, const float* __restrict__ w,
    const float* __restrict__ bias, float* __restrict__ h1)
{
    int b = blockIdx.x;
    __shared__ __align__(16) float xs[784];
    __shared__ __align__(16) float2 ws[450];
    __shared__ __align__(16) float bs[50];
    int tid = threadIdx.x;
    {
        const float4* xb = (const float4*)(x + (size_t)b * 784);
        for (int i = tid; i < 196; i += 192) ((float4*)xs)[i] = xb[i];
        for (int i = tid; i < 450; i += 192) { float v = w[i]; ws[i] = make_float2(v, v); }
        for (int i = tid; i < 50;  i += 192) bs[i] = bias[i];
    }
    __syncthreads();
    if (tid >= 169) return;

    const int py = tid / 13, px = tid % 13;
    const int Y = 2 * py, X = 2 * px;
    float p[4][4];
    #pragma unroll
    for (int r = 0; r < 4; r++)
        #pragma unroll
        for (int c = 0; c < 4; c++) p[r][c] = xs[(Y + r) * 28 + X + c];
    unsigned long long P[4][3];
    #pragma unroll
    for (int r = 0; r < 4; r++)
        #pragma unroll
        for (int k = 0; k < 3; k++)
            asm("mov.b64 %0, {%1, %2};" : "=l"(P[r][k])
                : "r"(__float_as_uint(p[r][k])), "r"(__float_as_uint(p[r][k + 1])));

    float* hb = h1 + (size_t)b * KP1P + tid;
    for (int oc = 0; oc < 50; oc++) {
        unsigned long long aT = 0ULL, aB = 0ULL;
        #pragma unroll
        for (int ky = 0; ky < 3; ky++)
            #pragma unroll
            for (int kx = 0; kx < 3; kx++) {
                unsigned long long w2 = *(const unsigned long long*)&ws[oc * 9 + ky * 3 + kx];
                asm("fma.rn.f32x2 %0, %1, %2, %0;" : "+l"(aT) : "l"(P[ky][kx]), "l"(w2));
                asm("fma.rn.f32x2 %0, %1, %2, %0;" : "+l"(aB) : "l"(P[ky + 1][kx]), "l"(w2));
            }
        unsigned int u0, u1, u2, u3;
        asm("mov.b64 {%0, %1}, %2;" : "=r"(u0), "=r"(u1) : "l"(aT));
        asm("mov.b64 {%0, %1}, %2;" : "=r"(u2), "=r"(u3) : "l"(aB));
        float m = fmaxf(fmaxf(__uint_as_float(u0), __uint_as_float(u1)),
                        fmaxf(__uint_as_float(u2), __uint_as_float(u3)));
        m += bs[oc];
        hb[oc * 169] = fmaxf(m, 0.f);
    }
}

// ====== stagehead common tile sizes =========================================
#define SH_G 16
#define SH_CK 512
#define SH_SMEM ((12 * SH_CK + SH_G * SH_CK) * 4)   // 56 KB

// ---- split-K partial variant (stage 1) --------------------------------------
__global__ __launch_bounds__(256) void stagehead_part_kernel(
    const float* __restrict__ f, int Kp,
    const float* __restrict__ W12, float* __restrict__ part)
{
    extern __shared__ __align__(16) float sh[];
    float* ws = sh;
    float* hs = sh + 12 * SH_CK;
    const int tid = threadIdx.x, lane = tid & 31, wid = tid >> 5;
    const int b0 = blockIdx.x * SH_G;
    const int split = blockIdx.y;
    const int s0 = wid * 2, s1 = s0 + 1;

    const int nch = Kp / SH_CK;
    const int half = (nch + 1) / 2;
    const int c0 = split * half;
    const int cE = min(nch, c0 + half);

    float acc0[12], acc1[12];
    #pragma unroll
    for (int j = 0; j < 12; j++) { acc0[j] = 0.f; acc1[j] = 0.f; }

    for (int c = c0; c < cE; c++) {
        const int kc = c * SH_CK;
        for (int i = tid; i < 12 * 128; i += 256) {
            int j = i >> 7, k4 = (i & 127) * 4;
            *(float4*)&ws[j * SH_CK + k4] = *(const float4*)&W12[(size_t)j * Kp + kc + k4];
        }
        for (int i = tid; i < SH_G * 128; i += 256) {
            int s = i >> 7, k4 = (i & 127) * 4;
            *(float4*)&hs[s * SH_CK + k4] = *(const float4*)&f[(size_t)(b0 + s) * Kp + kc + k4];
        }
        __syncthreads();

        #pragma unroll
        for (int it = 0; it < 4; it++) {
            const int kk = it * 128 + lane * 4;
            float4 f0 = *(float4*)&hs[s0 * SH_CK + kk];
            float4 f1 = *(float4*)&hs[s1 * SH_CK + kk];
            #pragma unroll
            for (int j = 0; j < 12; j++) {
                float4 w = *(float4*)&ws[j * SH_CK + kk];
                acc0[j] = fmaf(f0.x, w.x, fmaf(f0.y, w.y, fmaf(f0.z, w.z, fmaf(f0.w, w.w, acc0[j]))));
                acc1[j] = fmaf(f1.x, w.x, fmaf(f1.y, w.y, fmaf(f1.z, w.z, fmaf(f1.w, w.w, acc1[j]))));
            }
        }
        __syncthreads();
    }

    #pragma unroll
    for (int j = 0; j < 12; j++) {
        #pragma unroll
        for (int off = 16; off; off >>= 1) {
            acc0[j] += __shfl_xor_sync(0xffffffffu, acc0[j], off);
            acc1[j] += __shfl_xor_sync(0xffffffffu, acc1[j], off);
        }
    }
    if (lane == 0) {
        int ba = b0 + s0, bb = b0 + s1;
        #pragma unroll
        for (int j = 0; j < 12; j++) {
            part[ba * 24 + split * 12 + j] = acc0[j];
            part[bb * 24 + split * 12 + j] = acc1[j];
        }
    }
}

// ---- direct variant (stage 2) -----------------------------------------------
__global__ __launch_bounds__(256) void stagehead_kernel(
    const float* __restrict__ f, int Kp,
    const float* __restrict__ W12, const float* __restrict__ bc12,
    float* __restrict__ o, int* __restrict__ e)
{
    extern __shared__ __align__(16) float sh[];
    float* ws = sh;
    float* hs = sh + 12 * SH_CK;
    const int tid = threadIdx.x, lane = tid & 31, wid = tid >> 5;
    const int b0 = blockIdx.x * SH_G;
    const int s0 = wid * 2, s1 = s0 + 1;

    float acc0[12], acc1[12];
    #pragma unroll
    for (int j = 0; j < 12; j++) { acc0[j] = 0.f; acc1[j] = 0.f; }

    const int nchunks = Kp / SH_CK;
    for (int c = 0; c < nchunks; c++) {
        const int kc = c * SH_CK;
        for (int i = tid; i < 12 * 128; i += 256) {
            int j = i >> 7, k4 = (i & 127) * 4;
            *(float4*)&ws[j * SH_CK + k4] = *(const float4*)&W12[(size_t)j * Kp + kc + k4];
        }
        for (int i = tid; i < SH_G * 128; i += 256) {
            int s = i >> 7, k4 = (i & 127) * 4;
            *(float4*)&hs[s * SH_CK + k4] = *(const float4*)&f[(size_t)(b0 + s) * Kp + kc + k4];
        }
        __syncthreads();

        #pragma unroll
        for (int it = 0; it < 4; it++) {
            const int kk = it * 128 + lane * 4;
            float4 f0 = *(float4*)&hs[s0 * SH_CK + kk];
            float4 f1 = *(float4*)&hs[s1 * SH_CK + kk];
            #pragma unroll
            for (int j = 0; j < 12; j++) {
                float4 w = *(float4*)&ws[j * SH_CK + kk];
                acc0[j] = fmaf(f0.x, w.x, fmaf(f0.y, w.y, fmaf(f0.z, w.z, fmaf(f0.w, w.w, acc0[j]))));
                acc1[j] = fmaf(f1.x, w.x, fmaf(f1.y, w.y, fmaf(f1.z, w.z, fmaf(f1.w, w.w, acc1[j]))));
            }
        }
        __syncthreads();
    }

    #pragma unroll
    for (int j = 0; j < 12; j++) {
        #pragma unroll
        for (int off = 16; off; off >>= 1) {
            acc0[j] += __shfl_xor_sync(0xffffffffu, acc0[j], off);
            acc1[j] += __shfl_xor_sync(0xffffffffu, acc1[j], off);
        }
    }
    if (lane == 0) {
        int ba = b0 + s0, bb = b0 + s1;
        #pragma unroll
        for (int j = 0; j < 10; j++) {
            o[ba * 10 + j] = acc0[j] + bc12[j];
            o[bb * 10 + j] = acc1[j] + bc12[j];
        }
        e[ba] = (acc0[10] + bc12[10] >= acc0[11] + bc12[11]) ? 1 : 0;
        e[bb] = (acc1[10] + bc12[10] >= acc1[11] + bc12[11]) ? 1 : 0;
    }
}

// ---------------- conv2 v3: padded hs + LDS.128 weight tiles ----------------
// dynamic smem: hs[50][13][14] @0 (36416B) | wb[2][2500]f2 @36416 | bss @76416
#define C2_SMEM 76672
__global__ __launch_bounds__(256, 2) void conv2_kernel(
    const float* __restrict__ h1, const float2* __restrict__ wpk,
    const float* __restrict__ bias, float* __restrict__ h2,
    const float* __restrict__ part, const float* __restrict__ b1c,
    int* __restrict__ e1)
{
    extern __shared__ __align__(16) char csm[];
    float*  hs  = (float*)csm;                       // padded rows of 14
    float2* wb  = (float2*)(csm + 36416);            // [2][2500]
    float*  bss = (float*)(csm + 76416);             // [50]
    __shared__ int sflag;

    const int b = blockIdx.x;
    const int tid = threadIdx.x;
    if (tid == 0) {
        float m0 = part[b * 24 + 10] + part[b * 24 + 22] + __ldg(&b1c[10]);
        float m1 = part[b * 24 + 11] + part[b * 24 + 23] + __ldg(&b1c[11]);
        int fl = (m0 >= m1) ? 1 : 0;
        e1[b] = fl;
        sflag = fl;
    }
    __syncthreads();
    if (sflag) return;

    {
        const float* hb = h1 + (size_t)b * KP1P;
        for (int i = tid; i < 8450; i += 256) {
            int ic = i / 169, rem = i - ic * 169;
            int r = rem / 13, c = rem - r * 13;
            hs[ic * 182 + r * 14 + c] = hb[i];
        }
        for (int i = tid; i < 50; i += 256) bss[i] = bias[i];
        // weight tile 0 (5 ic = 1250 float4)
        for (int i = tid; i < 1250; i += 256)
            ((float4*)wb)[i] = ((const float4*)wpk)[i];
    }
    __syncthreads();

    const int osub = tid / 25, pos = tid % 25;
    const int oc0 = osub * 5;
    const int py = pos / 5, px = pos % 5;
    const int Y = 2 * py, X = 2 * px;
    const bool active = (tid < 250);

    unsigned long long aT[5], aB[5];
    #pragma unroll
    for (int j = 0; j < 5; j++) { aT[j] = 0ULL; aB[j] = 0ULL; }

    for (int t = 0; t < 10; t++) {
        const int cur = t & 1;
        if (t + 1 < 10) {
            const float4* src = (const float4*)wpk + (t + 1) * 1250;
            float4* dst = (float4*)(wb + (cur ^ 1) * 2500);
            for (int i = tid; i < 1250; i += 256) dst[i] = src[i];
        }
        if (active) {
            #pragma unroll
            for (int i5 = 0; i5 < 5; i5++) {
                const float* hc = hs + (t * 5 + i5) * 182;
                unsigned long long P[4][3];
                #pragma unroll
                for (int r = 0; r < 4; r++) {
                    float2 v0 = *(const float2*)(hc + (Y + r) * 14 + X);
                    float2 v1 = *(const float2*)(hc + (Y + r) * 14 + X + 2);
                    asm("mov.b64 %0, {%1, %2};" : "=l"(P[r][0])
                        : "r"(__float_as_uint(v0.x)), "r"(__float_as_uint(v0.y)));
                    asm("mov.b64 %0, {%1, %2};" : "=l"(P[r][1])
                        : "r"(__float_as_uint(v0.y)), "r"(__float_as_uint(v1.x)));
                    asm("mov.b64 %0, {%1, %2};" : "=l"(P[r][2])
                        : "r"(__float_as_uint(v1.x)), "r"(__float_as_uint(v1.y)));
                }
                const float2* wrow = wb + cur * 2500 + (i5 * 50 + oc0) * 10;
                #pragma unroll
                for (int j = 0; j < 5; j++) {
                    const float2* wp = wrow + j * 10;
                    ulonglong2 q0 = *(const ulonglong2*)(wp);
                    ulonglong2 q1 = *(const ulonglong2*)(wp + 2);
                    ulonglong2 q2 = *(const ulonglong2*)(wp + 4);
                    ulonglong2 q3 = *(const ulonglong2*)(wp + 6);
                    unsigned long long w8 = *(const unsigned long long*)(wp + 8);
                    unsigned long long wv[9] = {q0.x, q0.y, q1.x, q1.y,
                                                q2.x, q2.y, q3.x, q3.y, w8};
                    #pragma unroll
                    for (int ky = 0; ky < 3; ky++)
                        #pragma unroll
                        for (int kx = 0; kx < 3; kx++) {
                            asm("fma.rn.f32x2 %0, %1, %2, %0;"
                                : "+l"(aT[j]) : "l"(P[ky][kx]), "l"(wv[ky * 3 + kx]));
                            asm("fma.rn.f32x2 %0, %1, %2, %0;"
                                : "+l"(aB[j]) : "l"(P[ky + 1][kx]), "l"(wv[ky * 3 + kx]));
                        }
                }
            }
        }
        __syncthreads();
    }

    if (active) {
        #pragma unroll
        for (int j = 0; j < 5; j++) {
            unsigned int u0, u1, u2, u3;
            asm("mov.b64 {%0, %1}, %2;" : "=r"(u0), "=r"(u1) : "l"(aT[j]));
            asm("mov.b64 {%0, %1}, %2;" : "=r"(u2), "=r"(u3) : "l"(aB[j]));
            float m = fmaxf(fmaxf(__uint_as_float(u0), __uint_as_float(u1)),
                            fmaxf(__uint_as_float(u2), __uint_as_float(u3)));
            m += bss[oc0 + j];
            h2[(size_t)b * KP2P + (oc0 + j) * 25 + pos] = fmaxf(m, 0.f);
        }
    }
}

// ---------------- conv3 (skips samples exiting at 1 or 2) -------------------
__global__ void conv3_kernel(const float* __restrict__ h2,
                             const float* __restrict__ w,
                             const float* __restrict__ bias,
                             float* __restrict__ f3,
                             const int* __restrict__ e1,
                             const int* __restrict__ e2)
{
    int b = blockIdx.x;
    if (e1[b] || e2[b]) return;
    __shared__ __align__(16) float hs[1250];
    const float* hb = h2 + (size_t)b * KP2P;
    for (int i = threadIdx.x; i < 1250; i += blockDim.x) hs[i] = hb[i];
    __syncthreads();

    int oc = threadIdx.x;
    if (oc >= 50) return;
    float a0 = 0.f, a1 = 0.f, a2 = 0.f, a3 = 0.f;
    for (int ic = 0; ic < 50; ic++) {
        const float* hc = hs + ic * 25;
        #pragma unroll
        for (int ky = 0; ky < 3; ky++)
            #pragma unroll
            for (int kx = 0; kx < 3; kx++) {
                float wv = __ldg(&w[oc * 450 + ic * 9 + ky * 3 + kx]);
                a0 += hc[ky * 5 + kx] * wv;
                a1 += hc[ky * 5 + kx + 1] * wv;
                a2 += hc[(ky + 1) * 5 + kx] * wv;
                a3 += hc[(ky + 1) * 5 + kx + 1] * wv;
            }
    }
    float m = fmaxf(fmaxf(a0, a1), fmaxf(a2, a3)) + __ldg(&bias[oc]);
    f3[b * 50 + oc] = fmaxf(m, 0.f);
}

// ==== stage3 + final fused ===================================================
#define S3_G 32
#define S3_SMEM ((25000 + 5000 + 500 + S3_G * 50 + S3_G * 500 + S3_G * 10) * 4)

__global__ __launch_bounds__(256) void stage3final_kernel(
    const float* __restrict__ f3,
    const float* __restrict__ l1w, const float* __restrict__ l1b,
    const float* __restrict__ l2w, const float* __restrict__ l2b,
    const int* __restrict__ e1, const int* __restrict__ e2,
    const float* __restrict__ part, const float* __restrict__ b1c,
    const float* __restrict__ o2, float* __restrict__ out)
{
    extern __shared__ __align__(16) float sm[];
    float* w1  = sm;
    float* w2  = sm + 25000;
    float* b1  = sm + 30000;
    float* fs  = sm + 30500;
    float* hid = sm + 32100;
    float* o3s = sm + 48100;
    int tid = threadIdx.x;
    int b0 = blockIdx.x * S3_G;

    for (int i = tid; i < 25000; i += 256) w1[i] = l1w[i];
    for (int i = tid; i < 5000;  i += 256) w2[i] = l2w[i];
    for (int i = tid; i < 500;   i += 256) b1[i] = l1b[i];
    for (int i = tid; i < S3_G * 50; i += 256) fs[i] = f3[b0 * 50 + i];
    __syncthreads();

    for (int hh = tid; hh < S3_G * 500; hh += 256) {
        int s = hh / 500, j = hh - s * 500;
        float a = b1[j];
        const float* fr = fs + s * 50;
        const float* wr = w1 + j * 50;
        #pragma unroll 10
        for (int k = 0; k < 50; k++) a += fr[k] * wr[k];
        hid[hh] = fmaxf(a, 0.f);
    }
    __syncthreads();

    for (int oo = tid; oo < S3_G * 10; oo += 256) {
        int s = oo / 10, n = oo - s * 10;
        float a = __ldg(&l2b[n]);
        const float* hr = hid + s * 500;
        const float* wr = w2 + n * 500;
        #pragma unroll 4
        for (int j = 0; j < 500; j++) a += hr[j] * wr[j];
        o3s[s * 10 + n] = a;
    }
    __syncthreads();

    if (tid < S3_G) {
        int b = b0 + tid;
        float v[10];
        if (e1[b]) {
            #pragma unroll
            for (int j = 0; j < 10; j++)
                v[j] = part[b * 24 + j] + part[b * 24 + 12 + j] + __ldg(&b1c[j]);
        } else if (e2[b]) {
            #pragma unroll
            for (int j = 0; j < 10; j++) v[j] = o2[b * 10 + j];
        } else {
            #pragma unroll
            for (int j = 0; j < 10; j++) v[j] = o3s[tid * 10 + j];
        }
        float mx = -1e30f;
        #pragma unroll
        for (int j = 0; j < 10; j++) mx = fmaxf(mx, v[j]);
        float sum = 0.f;
        #pragma unroll
        for (int j = 0; j < 10; j++) sum += expf(v[j] - mx);
        float l = logf(sum);
        #pragma unroll
        for (int j = 0; j < 10; j++) out[b * 10 + j] = v[j] - mx - l;
    }
}

// ---------------- launch ----------------------------------------------------
extern "C" void kernel_launch(void* const* d_in, const int* in_sizes, int n_in,
                              void* d_out, int out_size)
{
    const float* x      = (const float*)d_in[0];
    const float* c1_w   = (const float*)d_in[1];
    const float* c1_b   = (const float*)d_in[2];
    const float* c2_w   = (const float*)d_in[3];
    const float* c2_b   = (const float*)d_in[4];
    const float* c3_w   = (const float*)d_in[5];
    const float* c3_b   = (const float*)d_in[6];
    const float* l1c1_w = (const float*)d_in[7];
    const float* l1c1_b = (const float*)d_in[8];
    const float* l2c1_w = (const float*)d_in[9];
    const float* l2c1_b = (const float*)d_in[10];
    const float* l1c2_w = (const float*)d_in[11];
    const float* l1c2_b = (const float*)d_in[12];
    const float* l2c2_w = (const float*)d_in[13];
    const float* l2c2_b = (const float*)d_in[14];
    const float* l1_w   = (const float*)d_in[15];
    const float* l1_b   = (const float*)d_in[16];
    const float* l2_w   = (const float*)d_in[17];
    const float* l2_b   = (const float*)d_in[18];
    const float* d1_w   = (const float*)d_in[19];
    const float* d1_b   = (const float*)d_in[20];
    const float* d2_w   = (const float*)d_in[21];
    const float* d2_b   = (const float*)d_in[22];
    float* out = (float*)d_out;

    float *h1, *h2, *f3, *o2, *W1, *W2, *b1c, *b2c, *part1;
    float2 *wpk2;
    int *e1, *e2;
    cudaGetSymbolAddress((void**)&h1,   g_h1);
    cudaGetSymbolAddress((void**)&h2,   g_h2);
    cudaGetSymbolAddress((void**)&f3,   g_f3);
    cudaGetSymbolAddress((void**)&o2,   g_o2);
    cudaGetSymbolAddress((void**)&e1,   g_e1);
    cudaGetSymbolAddress((void**)&e2,   g_e2);
    cudaGetSymbolAddress((void**)&W1,   g_W1);
    cudaGetSymbolAddress((void**)&W2,   g_W2);
    cudaGetSymbolAddress((void**)&b1c,  g_b1c);
    cudaGetSymbolAddress((void**)&b2c,  g_b2c);
    cudaGetSymbolAddress((void**)&part1, g_part1);
    cudaGetSymbolAddress((void**)&wpk2, g_wpk2);

    static cudaStream_t s2 = nullptr;
    static cudaEvent_t evA = nullptr, evB = nullptr;
    static int attr_set = 0;
    if (!attr_set) {
        cudaFuncSetAttribute(stagehead_part_kernel,
                             cudaFuncAttributeMaxDynamicSharedMemorySize, SH_SMEM);
        cudaFuncSetAttribute(stagehead_kernel,
                             cudaFuncAttributeMaxDynamicSharedMemorySize, SH_SMEM);
        cudaFuncSetAttribute(conv2_kernel,
                             cudaFuncAttributeMaxDynamicSharedMemorySize, C2_SMEM);
        cudaFuncSetAttribute(stage3final_kernel,
                             cudaFuncAttributeMaxDynamicSharedMemorySize, S3_SMEM);
        cudaStreamCreateWithFlags(&s2, cudaStreamNonBlocking);
        cudaEventCreateWithFlags(&evA, cudaEventDisableTiming);
        cudaEventCreateWithFlags(&evB, cudaEventDisableTiming);
        attr_set = 1;
    }

    // fork: prep on side stream, conv1 on main stream (independent)
    cudaEventRecord(evA, 0);
    cudaStreamWaitEvent(s2, evA, 0);
    prep_kernel<<<128, 256, 0, s2>>>(l1c1_w, l1c1_b, l2c1_w, l2c1_b,
                                     l1c2_w, l1c2_b, l2c2_w, l2c2_b,
                                     d1_w, d1_b, d2_w, d2_b, c2_w,
                                     W1, b1c, W2, b2c, wpk2);
    cudaEventRecord(evB, s2);

    conv1_kernel<<<BATCH, 192>>>(x, c1_w, c1_b, h1);

    // join: sh1 needs W1 (prep) + h1 (conv1)
    cudaStreamWaitEvent(0, evB, 0);
    stagehead_part_kernel<<<dim3(BATCH / SH_G, 2), 256, SH_SMEM>>>(h1, KP1P, W1, part1);

    // stage 2 (conv2 derives e1 from partials)
    conv2_kernel<<<BATCH, 256, C2_SMEM>>>(h1, wpk2, c2_b, h2, part1, b1c, e1);
    stagehead_kernel<<<BATCH / SH_G, 256, SH_SMEM>>>(h2, KP2P, W2, b2c, o2, e2);

    // stage 3 + final select/log_softmax
    conv3_kernel<<<BATCH, 64>>>(h2, c3_w, c3_b, f3, e1, e2);
    stage3final_kernel<<<BATCH / S3_G, 256, S3_SMEM>>>(
        f3, l1_w, l1_b, l2_w, l2_b, e1, e2, part1, b1c, o2, out);
}

// round 10
// speedup vs baseline: 1.1859x; 1.0139x over previous
#include <cuda_runtime.h>
#include <math.h>
#include <stdint.h>

#define BATCH 4096
#define K1 8450
#define K2 1250
#define KP1P 8704          // h1 row pitch (17 * 512)
#define KP2P 1536          // h2 row pitch (3 * 512)

// ---------------- scratch (device globals; zero-initialized) ---------------
__device__ float g_h1[(size_t)BATCH * KP1P];
__device__ float g_h2[(size_t)BATCH * KP2P];
__device__ float g_f3[BATCH * 50];
__device__ float g_o2[BATCH * 10];
__device__ int   g_e1[BATCH];
__device__ int   g_e2[BATCH];
__device__ float g_W1[12 * KP1P];    // rows 0-9: l2c1@l1c1; 10-11: d1_w
__device__ float g_W2[12 * KP2P];
__device__ float g_b1c[12];
__device__ float g_b2c[12];
__device__ float g_part1[BATCH * 24];  // [b][split(2)][12]
__device__ float2 g_wpk2[50 * 500];    // conv2 weights [ic][oc][10] dup, pad k=9 zero

// ================= merged prep kernel =======================================
__device__ void combine_part(
    const float* __restrict__ l1, const float* __restrict__ b1,
    const float* __restrict__ l2, const float* __restrict__ b2,
    const float* __restrict__ dw, const float* __restrict__ db,
    int K, int Kp, float* __restrict__ W12, float* __restrict__ bc12,
    int blk, float* l2T)
{
    int tid = threadIdx.x;
    for (int i = tid; i < 5000; i += 256) {
        int j = i / 500, r = i - j * 500;
        l2T[r * 12 + j] = l2[i];
    }
    for (int r = tid; r < 500; r += 256) { l2T[r * 12 + 10] = 0.f; l2T[r * 12 + 11] = 0.f; }
    __syncthreads();

    int k = blk * 256 + tid;
    if (k < Kp) {
        if (k < K) {
            float acc[10];
            #pragma unroll
            for (int j = 0; j < 10; j++) acc[j] = 0.f;
            #pragma unroll 4
            for (int r = 0; r < 500; r++) {
                float a = __ldg(&l1[(size_t)r * K + k]);
                float4 w0 = *(const float4*)&l2T[r * 12];
                float4 w1 = *(const float4*)&l2T[r * 12 + 4];
                float2 w2 = *(const float2*)&l2T[r * 12 + 8];
                acc[0] += a * w0.x; acc[1] += a * w0.y; acc[2] += a * w0.z; acc[3] += a * w0.w;
                acc[4] += a * w1.x; acc[5] += a * w1.y; acc[6] += a * w1.z; acc[7] += a * w1.w;
                acc[8] += a * w2.x; acc[9] += a * w2.y;
            }
            #pragma unroll
            for (int j = 0; j < 10; j++) W12[(size_t)j * Kp + k] = acc[j];
            W12[(size_t)10 * Kp + k] = __ldg(&dw[k]);
            W12[(size_t)11 * Kp + k] = __ldg(&dw[K + k]);
        } else {
            #pragma unroll
            for (int j = 0; j < 12; j++) W12[(size_t)j * Kp + k] = 0.f;
        }
    }
    if (blk == 0) {
        if (tid < 10) {
            float a = b2[tid];
            for (int r = 0; r < 500; r++) a += l2[tid * 500 + r] * b1[r];
            bc12[tid] = a;
        } else if (tid < 12) {
            bc12[tid] = db[tid - 10];
        }
    }
}

__global__ __launch_bounds__(256) void prep_kernel(
    const float* l1c1_w, const float* l1c1_b, const float* l2c1_w, const float* l2c1_b,
    const float* l1c2_w, const float* l1c2_b, const float* l2c2_w, const float* l2c2_b,
    const float* d1_w, const float* d1_b, const float* d2_w, const float* d2_b,
    const float* c2_w,
    float* W1, float* b1c, float* W2, float* b2c, float2* wpk2)
{
    __shared__ __align__(16) float l2T[500 * 12];
    int bx = blockIdx.x, tid = threadIdx.x;
    if (bx < 34) {
        combine_part(l1c1_w, l1c1_b, l2c1_w, l2c1_b, d1_w, d1_b, K1, KP1P, W1, b1c, bx, l2T);
    } else if (bx < 40) {
        combine_part(l1c2_w, l1c2_b, l2c2_w, l2c2_b, d2_w, d2_b, K2, KP2P, W2, b2c, bx - 34, l2T);
    } else {
        int i = (bx - 40) * 256 + tid;
        if (i < 22500) {
            int oc = i / 450, r = i - oc * 450;
            int ic = r / 9, k = r - ic * 9;
            float v = c2_w[i];
            wpk2[ic * 500 + oc * 10 + k] = make_float2(v, v);   // pad k=9 stays zero
        }
    }
}

// ---------------- conv1: register patch + packed f32x2 ----------------------
__global__ __launch_bounds__(192) void conv1_kernel(
    const float* __restrict__ x, const float* __restrict__ w,
    const float* __restrict__ bias, float* __restrict__ h1)
{
    int b = blockIdx.x;
    __shared__ __align__(16) float xs[784];
    __shared__ __align__(16) float2 ws[450];
    __shared__ __align__(16) float bs[50];
    int tid = threadIdx.x;
    {
        const float4* xb = (const float4*)(x + (size_t)b * 784);
        for (int i = tid; i < 196; i += 192) ((float4*)xs)[i] = xb[i];
        for (int i = tid; i < 450; i += 192) { float v = w[i]; ws[i] = make_float2(v, v); }
        for (int i = tid; i < 50;  i += 192) bs[i] = bias[i];
    }
    __syncthreads();
    if (tid >= 169) return;

    const int py = tid / 13, px = tid % 13;
    const int Y = 2 * py, X = 2 * px;
    float p[4][4];
    #pragma unroll
    for (int r = 0; r < 4; r++)
        #pragma unroll
        for (int c = 0; c < 4; c++) p[r][c] = xs[(Y + r) * 28 + X + c];
    unsigned long long P[4][3];
    #pragma unroll
    for (int r = 0; r < 4; r++)
        #pragma unroll
        for (int k = 0; k < 3; k++)
            asm("mov.b64 %0, {%1, %2};" : "=l"(P[r][k])
                : "r"(__float_as_uint(p[r][k])), "r"(__float_as_uint(p[r][k + 1])));

    float* hb = h1 + (size_t)b * KP1P + tid;
    for (int oc = 0; oc < 50; oc++) {
        unsigned long long aT = 0ULL, aB = 0ULL;
        #pragma unroll
        for (int ky = 0; ky < 3; ky++)
            #pragma unroll
            for (int kx = 0; kx < 3; kx++) {
                unsigned long long w2 = *(const unsigned long long*)&ws[oc * 9 + ky * 3 + kx];
                asm("fma.rn.f32x2 %0, %1, %2, %0;" : "+l"(aT) : "l"(P[ky][kx]), "l"(w2));
                asm("fma.rn.f32x2 %0, %1, %2, %0;" : "+l"(aB) : "l"(P[ky + 1][kx]), "l"(w2));
            }
        unsigned int u0, u1, u2, u3;
        asm("mov.b64 {%0, %1}, %2;" : "=r"(u0), "=r"(u1) : "l"(aT));
        asm("mov.b64 {%0, %1}, %2;" : "=r"(u2), "=r"(u3) : "l"(aB));
        float m = fmaxf(fmaxf(__uint_as_float(u0), __uint_as_float(u1)),
                        fmaxf(__uint_as_float(u2), __uint_as_float(u3)));
        m += bs[oc];
        hb[oc * 169] = fmaxf(m, 0.f);
    }
}

// ====== stagehead (stage 1 only): split-K partials ==========================
#define SH_G 16
#define SH_CK 512
#define SH_SMEM ((12 * SH_CK + SH_G * SH_CK) * 4)   // 56 KB

__global__ __launch_bounds__(256) void stagehead_part_kernel(
    const float* __restrict__ f, int Kp,
    const float* __restrict__ W12, float* __restrict__ part)
{
    extern __shared__ __align__(16) float sh[];
    float* ws = sh;
    float* hs = sh + 12 * SH_CK;
    const int tid = threadIdx.x, lane = tid & 31, wid = tid >> 5;
    const int b0 = blockIdx.x * SH_G;
    const int split = blockIdx.y;
    const int s0 = wid * 2, s1 = s0 + 1;

    const int nch = Kp / SH_CK;
    const int half = (nch + 1) / 2;
    const int c0 = split * half;
    const int cE = min(nch, c0 + half);

    float acc0[12], acc1[12];
    #pragma unroll
    for (int j = 0; j < 12; j++) { acc0[j] = 0.f; acc1[j] = 0.f; }

    for (int c = c0; c < cE; c++) {
        const int kc = c * SH_CK;
        for (int i = tid; i < 12 * 128; i += 256) {
            int j = i >> 7, k4 = (i & 127) * 4;
            *(float4*)&ws[j * SH_CK + k4] = *(const float4*)&W12[(size_t)j * Kp + kc + k4];
        }
        for (int i = tid; i < SH_G * 128; i += 256) {
            int s = i >> 7, k4 = (i & 127) * 4;
            *(float4*)&hs[s * SH_CK + k4] = *(const float4*)&f[(size_t)(b0 + s) * Kp + kc + k4];
        }
        __syncthreads();

        #pragma unroll
        for (int it = 0; it < 4; it++) {
            const int kk = it * 128 + lane * 4;
            float4 f0 = *(float4*)&hs[s0 * SH_CK + kk];
            float4 f1 = *(float4*)&hs[s1 * SH_CK + kk];
            #pragma unroll
            for (int j = 0; j < 12; j++) {
                float4 w = *(float4*)&ws[j * SH_CK + kk];
                acc0[j] = fmaf(f0.x, w.x, fmaf(f0.y, w.y, fmaf(f0.z, w.z, fmaf(f0.w, w.w, acc0[j]))));
                acc1[j] = fmaf(f1.x, w.x, fmaf(f1.y, w.y, fmaf(f1.z, w.z, fmaf(f1.w, w.w, acc1[j]))));
            }
        }
        __syncthreads();
    }

    #pragma unroll
    for (int j = 0; j < 12; j++) {
        #pragma unroll
        for (int off = 16; off; off >>= 1) {
            acc0[j] += __shfl_xor_sync(0xffffffffu, acc0[j], off);
            acc1[j] += __shfl_xor_sync(0xffffffffu, acc1[j], off);
        }
    }
    if (lane == 0) {
        int ba = b0 + s0, bb = b0 + s1;
        #pragma unroll
        for (int j = 0; j < 12; j++) {
            part[ba * 24 + split * 12 + j] = acc0[j];
            part[bb * 24 + split * 12 + j] = acc1[j];
        }
    }
}

// ---------------- conv2 + fused stage-2 head --------------------------------
// dyn smem: hs[50][13][14] @0 | wb[2][2500]f2 @36416 | bss @76416 | red @76624
#define C2_SMEM 77056
__global__ __launch_bounds__(256, 2) void conv2_kernel(
    const float* __restrict__ h1, const float2* __restrict__ wpk,
    const float* __restrict__ bias, float* __restrict__ h2,
    const float* __restrict__ part, const float* __restrict__ b1c,
    const float* __restrict__ W2, const float* __restrict__ b2c,
    int* __restrict__ e1, int* __restrict__ e2, float* __restrict__ o2)
{
    extern __shared__ __align__(16) char csm[];
    float*  hs  = (float*)csm;                       // padded rows of 14
    float2* wb  = (float2*)(csm + 36416);            // [2][2500]
    float*  bss = (float*)(csm + 76416);             // [50]
    float*  red = (float*)(csm + 76624);             // [12][8] + [12]
    __shared__ int sflag;

    const int b = blockIdx.x;
    const int tid = threadIdx.x;
    if (tid == 0) {
        float m0 = part[b * 24 + 10] + part[b * 24 + 22] + __ldg(&b1c[10]);
        float m1 = part[b * 24 + 11] + part[b * 24 + 23] + __ldg(&b1c[11]);
        int fl = (m0 >= m1) ? 1 : 0;
        e1[b] = fl;
        sflag = fl;
        if (fl) e2[b] = 0;     // deterministic; value unused for e1 samples
    }
    __syncthreads();
    if (sflag) return;

    {
        const float* hb = h1 + (size_t)b * KP1P;
        for (int i = tid; i < 8450; i += 256) {
            int ic = i / 169, rem = i - ic * 169;
            int r = rem / 13, c = rem - r * 13;
            hs[ic * 182 + r * 14 + c] = hb[i];
        }
        for (int i = tid; i < 50; i += 256) bss[i] = bias[i];
        for (int i = tid; i < 1250; i += 256)
            ((float4*)wb)[i] = ((const float4*)wpk)[i];
    }
    __syncthreads();

    const int osub = tid / 25, pos = tid % 25;
    const int oc0 = osub * 5;
    const int py = pos / 5, px = pos % 5;
    const int Y = 2 * py, X = 2 * px;
    const bool active = (tid < 250);

    unsigned long long aT[5], aB[5];
    #pragma unroll
    for (int j = 0; j < 5; j++) { aT[j] = 0ULL; aB[j] = 0ULL; }

    for (int t = 0; t < 10; t++) {
        const int cur = t & 1;
        if (t + 1 < 10) {
            const float4* src = (const float4*)wpk + (t + 1) * 1250;
            float4* dst = (float4*)(wb + (cur ^ 1) * 2500);
            for (int i = tid; i < 1250; i += 256) dst[i] = src[i];
        }
        if (active) {
            #pragma unroll
            for (int i5 = 0; i5 < 5; i5++) {
                const float* hc = hs + (t * 5 + i5) * 182;
                unsigned long long P[4][3];
                #pragma unroll
                for (int r = 0; r < 4; r++) {
                    float2 v0 = *(const float2*)(hc + (Y + r) * 14 + X);
                    float2 v1 = *(const float2*)(hc + (Y + r) * 14 + X + 2);
                    asm("mov.b64 %0, {%1, %2};" : "=l"(P[r][0])
                        : "r"(__float_as_uint(v0.x)), "r"(__float_as_uint(v0.y)));
                    asm("mov.b64 %0, {%1, %2};" : "=l"(P[r][1])
                        : "r"(__float_as_uint(v0.y)), "r"(__float_as_uint(v1.x)));
                    asm("mov.b64 %0, {%1, %2};" : "=l"(P[r][2])
                        : "r"(__float_as_uint(v1.x)), "r"(__float_as_uint(v1.y)));
                }
                const float2* wrow = wb + cur * 2500 + (i5 * 50 + oc0) * 10;
                #pragma unroll
                for (int j = 0; j < 5; j++) {
                    const float2* wp = wrow + j * 10;
                    ulonglong2 q0 = *(const ulonglong2*)(wp);
                    ulonglong2 q1 = *(const ulonglong2*)(wp + 2);
                    ulonglong2 q2 = *(const ulonglong2*)(wp + 4);
                    ulonglong2 q3 = *(const ulonglong2*)(wp + 6);
                    unsigned long long w8 = *(const unsigned long long*)(wp + 8);
                    unsigned long long wv[9] = {q0.x, q0.y, q1.x, q1.y,
                                                q2.x, q2.y, q3.x, q3.y, w8};
                    #pragma unroll
                    for (int ky = 0; ky < 3; ky++)
                        #pragma unroll
                        for (int kx = 0; kx < 3; kx++) {
                            asm("fma.rn.f32x2 %0, %1, %2, %0;"
                                : "+l"(aT[j]) : "l"(P[ky][kx]), "l"(wv[ky * 3 + kx]));
                            asm("fma.rn.f32x2 %0, %1, %2, %0;"
                                : "+l"(aB[j]) : "l"(P[ky + 1][kx]), "l"(wv[ky * 3 + kx]));
                        }
                }
            }
        }
        __syncthreads();
    }

    // finalize conv outputs + per-thread head partials
    float hd[12];
    #pragma unroll
    for (int jj = 0; jj < 12; jj++) hd[jj] = 0.f;
    if (active) {
        float v5[5];
        #pragma unroll
        for (int j = 0; j < 5; j++) {
            unsigned int u0, u1, u2, u3;
            asm("mov.b64 {%0, %1}, %2;" : "=r"(u0), "=r"(u1) : "l"(aT[j]));
            asm("mov.b64 {%0, %1}, %2;" : "=r"(u2), "=r"(u3) : "l"(aB[j]));
            float m = fmaxf(fmaxf(__uint_as_float(u0), __uint_as_float(u1)),
                            fmaxf(__uint_as_float(u2), __uint_as_float(u3)));
            m += bss[oc0 + j];
            v5[j] = fmaxf(m, 0.f);
            h2[(size_t)b * KP2P + (oc0 + j) * 25 + pos] = v5[j];
        }
        #pragma unroll
        for (int jj = 0; jj < 12; jj++) {
            float s = 0.f;
            #pragma unroll
            for (int j = 0; j < 5; j++)
                s += v5[j] * __ldg(&W2[(size_t)jj * KP2P + (oc0 + j) * 25 + pos]);
            hd[jj] = s;
        }
    }
    // block reduce 12 sums
    const int lane = tid & 31, wrp = tid >> 5;
    #pragma unroll
    for (int jj = 0; jj < 12; jj++) {
        #pragma unroll
        for (int off = 16; off; off >>= 1)
            hd[jj] += __shfl_xor_sync(0xffffffffu, hd[jj], off);
    }
    if (lane == 0) {
        #pragma unroll
        for (int jj = 0; jj < 12; jj++) red[jj * 8 + wrp] = hd[jj];
    }
    __syncthreads();
    if (tid < 12) {
        float s = __ldg(&b2c[tid]);
        #pragma unroll
        for (int w = 0; w < 8; w++) s += red[tid * 8 + w];
        red[96 + tid] = s;
    }
    __syncthreads();
    if (tid == 0) e2[b] = (red[96 + 10] >= red[96 + 11]) ? 1 : 0;
    if (tid < 10) o2[b * 10 + tid] = red[96 + tid];
}

// ---------------- conv3 (skips samples exiting at 1 or 2) -------------------
__global__ void conv3_kernel(const float* __restrict__ h2,
                             const float* __restrict__ w,
                             const float* __restrict__ bias,
                             float* __restrict__ f3,
                             const int* __restrict__ e1,
                             const int* __restrict__ e2)
{
    int b = blockIdx.x;
    if (e1[b] || e2[b]) return;
    __shared__ __align__(16) float hs[1250];
    const float* hb = h2 + (size_t)b * KP2P;
    for (int i = threadIdx.x; i < 1250; i += blockDim.x) hs[i] = hb[i];
    __syncthreads();

    int oc = threadIdx.x;
    if (oc >= 50) return;
    float a0 = 0.f, a1 = 0.f, a2 = 0.f, a3 = 0.f;
    for (int ic = 0; ic < 50; ic++) {
        const float* hc = hs + ic * 25;
        #pragma unroll
        for (int ky = 0; ky < 3; ky++)
            #pragma unroll
            for (int kx = 0; kx < 3; kx++) {
                float wv = __ldg(&w[oc * 450 + ic * 9 + ky * 3 + kx]);
                a0 += hc[ky * 5 + kx] * wv;
                a1 += hc[ky * 5 + kx + 1] * wv;
                a2 += hc[(ky + 1) * 5 + kx] * wv;
                a3 += hc[(ky + 1) * 5 + kx + 1] * wv;
            }
    }
    float m = fmaxf(fmaxf(a0, a1), fmaxf(a2, a3)) + __ldg(&bias[oc]);
    f3[b * 50 + oc] = fmaxf(m, 0.f);
}

// ==== stage3 + final fused ===================================================
#define S3_G 32
#define S3_SMEM ((25000 + 5000 + 500 + S3_G * 50 + S3_G * 500 + S3_G * 10) * 4)

__global__ __launch_bounds__(256) void stage3final_kernel(
    const float* __restrict__ f3,
    const float* __restrict__ l1w, const float* __restrict__ l1b,
    const float* __restrict__ l2w, const float* __restrict__ l2b,
    const int* __restrict__ e1, const int* __restrict__ e2,
    const float* __restrict__ part, const float* __restrict__ b1c,
    const float* __restrict__ o2, float* __restrict__ out)
{
    extern __shared__ __align__(16) float sm[];
    float* w1  = sm;
    float* w2  = sm + 25000;
    float* b1  = sm + 30000;
    float* fs  = sm + 30500;
    float* hid = sm + 32100;
    float* o3s = sm + 48100;
    int tid = threadIdx.x;
    int b0 = blockIdx.x * S3_G;

    for (int i = tid; i < 25000; i += 256) w1[i] = l1w[i];
    for (int i = tid; i < 5000;  i += 256) w2[i] = l2w[i];
    for (int i = tid; i < 500;   i += 256) b1[i] = l1b[i];
    for (int i = tid; i < S3_G * 50; i += 256) fs[i] = f3[b0 * 50 + i];
    __syncthreads();

    for (int hh = tid; hh < S3_G * 500; hh += 256) {
        int s = hh / 500, j = hh - s * 500;
        float a = b1[j];
        const float* fr = fs + s * 50;
        const float* wr = w1 + j * 50;
        #pragma unroll 10
        for (int k = 0; k < 50; k++) a += fr[k] * wr[k];
        hid[hh] = fmaxf(a, 0.f);
    }
    __syncthreads();

    for (int oo = tid; oo < S3_G * 10; oo += 256) {
        int s = oo / 10, n = oo - s * 10;
        float a = __ldg(&l2b[n]);
        const float* hr = hid + s * 500;
        const float* wr = w2 + n * 500;
        #pragma unroll 4
        for (int j = 0; j < 500; j++) a += hr[j] * wr[j];
        o3s[s * 10 + n] = a;
    }
    __syncthreads();

    if (tid < S3_G) {
        int b = b0 + tid;
        float v[10];
        if (e1[b]) {
            #pragma unroll
            for (int j = 0; j < 10; j++)
                v[j] = part[b * 24 + j] + part[b * 24 + 12 + j] + __ldg(&b1c[j]);
        } else if (e2[b]) {
            #pragma unroll
            for (int j = 0; j < 10; j++) v[j] = o2[b * 10 + j];
        } else {
            #pragma unroll
            for (int j = 0; j < 10; j++) v[j] = o3s[tid * 10 + j];
        }
        float mx = -1e30f;
        #pragma unroll
        for (int j = 0; j < 10; j++) mx = fmaxf(mx, v[j]);
        float sum = 0.f;
        #pragma unroll
        for (int j = 0; j < 10; j++) sum += expf(v[j] - mx);
        float l = logf(sum);
        #pragma unroll
        for (int j = 0; j < 10; j++) out[b * 10 + j] = v[j] - mx - l;
    }
}

// ---------------- launch ----------------------------------------------------
extern "C" void kernel_launch(void* const* d_in, const int* in_sizes, int n_in,
                              void* d_out, int out_size)
{
    const float* x      = (const float*)d_in[0];
    const float* c1_w   = (const float*)d_in[1];
    const float* c1_b   = (const float*)d_in[2];
    const float* c2_w   = (const float*)d_in[3];
    const float* c2_b   = (const float*)d_in[4];
    const float* c3_w   = (const float*)d_in[5];
    const float* c3_b   = (const float*)d_in[6];
    const float* l1c1_w = (const float*)d_in[7];
    const float* l1c1_b = (const float*)d_in[8];
    const float* l2c1_w = (const float*)d_in[9];
    const float* l2c1_b = (const float*)d_in[10];
    const float* l1c2_w = (const float*)d_in[11];
    const float* l1c2_b = (const float*)d_in[12];
    const float* l2c2_w = (const float*)d_in[13];
    const float* l2c2_b = (const float*)d_in[14];
    const float* l1_w   = (const float*)d_in[15];
    const float* l1_b   = (const float*)d_in[16];
    const float* l2_w   = (const float*)d_in[17];
    const float* l2_b   = (const float*)d_in[18];
    const float* d1_w   = (const float*)d_in[19];
    const float* d1_b   = (const float*)d_in[20];
    const float* d2_w   = (const float*)d_in[21];
    const float* d2_b   = (const float*)d_in[22];
    float* out = (float*)d_out;

    float *h1, *h2, *f3, *o2, *W1, *W2, *b1c, *b2c, *part1;
    float2 *wpk2;
    int *e1, *e2;
    cudaGetSymbolAddress((void**)&h1,   g_h1);
    cudaGetSymbolAddress((void**)&h2,   g_h2);
    cudaGetSymbolAddress((void**)&f3,   g_f3);
    cudaGetSymbolAddress((void**)&o2,   g_o2);
    cudaGetSymbolAddress((void**)&e1,   g_e1);
    cudaGetSymbolAddress((void**)&e2,   g_e2);
    cudaGetSymbolAddress((void**)&W1,   g_W1);
    cudaGetSymbolAddress((void**)&W2,   g_W2);
    cudaGetSymbolAddress((void**)&b1c,  g_b1c);
    cudaGetSymbolAddress((void**)&b2c,  g_b2c);
    cudaGetSymbolAddress((void**)&part1, g_part1);
    cudaGetSymbolAddress((void**)&wpk2, g_wpk2);

    static cudaStream_t s2 = nullptr;
    static cudaEvent_t evA = nullptr, evB = nullptr;
    static int attr_set = 0;
    if (!attr_set) {
        cudaFuncSetAttribute(stagehead_part_kernel,
                             cudaFuncAttributeMaxDynamicSharedMemorySize, SH_SMEM);
        cudaFuncSetAttribute(conv2_kernel,
                             cudaFuncAttributeMaxDynamicSharedMemorySize, C2_SMEM);
        cudaFuncSetAttribute(stage3final_kernel,
                             cudaFuncAttributeMaxDynamicSharedMemorySize, S3_SMEM);
        cudaStreamCreateWithFlags(&s2, cudaStreamNonBlocking);
        cudaEventCreateWithFlags(&evA, cudaEventDisableTiming);
        cudaEventCreateWithFlags(&evB, cudaEventDisableTiming);
        attr_set = 1;
    }

    // fork: prep on side stream, conv1 on main stream (independent)
    cudaEventRecord(evA, 0);
    cudaStreamWaitEvent(s2, evA, 0);
    prep_kernel<<<128, 256, 0, s2>>>(l1c1_w, l1c1_b, l2c1_w, l2c1_b,
                                     l1c2_w, l1c2_b, l2c2_w, l2c2_b,
                                     d1_w, d1_b, d2_w, d2_b, c2_w,
                                     W1, b1c, W2, b2c, wpk2);
    cudaEventRecord(evB, s2);

    conv1_kernel<<<BATCH, 192>>>(x, c1_w, c1_b, h1);

    // join: sh1 needs W1 (prep) + h1 (conv1)
    cudaStreamWaitEvent(0, evB, 0);
    stagehead_part_kernel<<<dim3(BATCH / SH_G, 2), 256, SH_SMEM>>>(h1, KP1P, W1, part1);

    // stage 2: conv2 derives e1, computes h2, and fused head -> o2/e2
    conv2_kernel<<<BATCH, 256, C2_SMEM>>>(h1, wpk2, c2_b, h2, part1, b1c,
                                          W2, b2c, e1, e2, o2);

    // stage 3 + final select/log_softmax
    conv3_kernel<<<BATCH, 64>>>(h2, c3_w, c3_b, f3, e1, e2);
    stage3final_kernel<<<BATCH / S3_G, 256, S3_SMEM>>>(
        f3, l1_w, l1_b, l2_w, l2_b, e1, e2, part1, b1c, o2, out);
}

// round 11
// speedup vs baseline: 1.2210x; 1.0296x over previous
#include <cuda_runtime.h>
#include <math.h>
#include <stdint.h>

#define BATCH 4096
#define K1 8450
#define K2 1250
#define KP1P 8704          // h1 row pitch (17 * 512)
#define KP2P 1536          // h2 row pitch (3 * 512)

// ---------------- scratch (device globals; zero-initialized) ---------------
__device__ float g_h1[(size_t)BATCH * KP1P];
__device__ float g_h2[(size_t)BATCH * KP2P];
__device__ float g_f3[BATCH * 50];
__device__ float g_o2[BATCH * 10];
__device__ int   g_e1[BATCH];
__device__ int   g_e2[BATCH];
__device__ float g_W1[12 * KP1P];    // rows 0-9: l2c1@l1c1; 10-11: d1_w
__device__ float g_W2[12 * KP2P];
__device__ float g_b1c[12];
__device__ float g_b2c[12];
__device__ float g_part1[BATCH * 24];  // [b][split(2)][12]
__device__ float2 g_wpk2[50 * 500];    // conv2 weights [ic][oc][10] dup, pad k=9 zero

// ================= merged prep kernel =======================================
__device__ void combine_part(
    const float* __restrict__ l1, const float* __restrict__ b1,
    const float* __restrict__ l2, const float* __restrict__ b2,
    const float* __restrict__ dw, const float* __restrict__ db,
    int K, int Kp, float* __restrict__ W12, float* __restrict__ bc12,
    int blk, float* l2T)
{
    int tid = threadIdx.x;
    for (int i = tid; i < 5000; i += 256) {
        int j = i / 500, r = i - j * 500;
        l2T[r * 12 + j] = l2[i];
    }
    for (int r = tid; r < 500; r += 256) { l2T[r * 12 + 10] = 0.f; l2T[r * 12 + 11] = 0.f; }
    __syncthreads();

    int k = blk * 256 + tid;
    if (k < Kp) {
        if (k < K) {
            float acc[10];
            #pragma unroll
            for (int j = 0; j < 10; j++) acc[j] = 0.f;
            #pragma unroll 4
            for (int r = 0; r < 500; r++) {
                float a = __ldg(&l1[(size_t)r * K + k]);
                float4 w0 = *(const float4*)&l2T[r * 12];
                float4 w1 = *(const float4*)&l2T[r * 12 + 4];
                float2 w2 = *(const float2*)&l2T[r * 12 + 8];
                acc[0] += a * w0.x; acc[1] += a * w0.y; acc[2] += a * w0.z; acc[3] += a * w0.w;
                acc[4] += a * w1.x; acc[5] += a * w1.y; acc[6] += a * w1.z; acc[7] += a * w1.w;
                acc[8] += a * w2.x; acc[9] += a * w2.y;
            }
            #pragma unroll
            for (int j = 0; j < 10; j++) W12[(size_t)j * Kp + k] = acc[j];
            W12[(size_t)10 * Kp + k] = __ldg(&dw[k]);
            W12[(size_t)11 * Kp + k] = __ldg(&dw[K + k]);
        } else {
            #pragma unroll
            for (int j = 0; j < 12; j++) W12[(size_t)j * Kp + k] = 0.f;
        }
    }
    if (blk == 0) {
        if (tid < 10) {
            float a = b2[tid];
            for (int r = 0; r < 500; r++) a += l2[tid * 500 + r] * b1[r];
            bc12[tid] = a;
        } else if (tid < 12) {
            bc12[tid] = db[tid - 10];
        }
    }
}

__global__ __launch_bounds__(256) void prep_kernel(
    const float* l1c1_w, const float* l1c1_b, const float* l2c1_w, const float* l2c1_b,
    const float* l1c2_w, const float* l1c2_b, const float* l2c2_w, const float* l2c2_b,
    const float* d1_w, const float* d1_b, const float* d2_w, const float* d2_b,
    const float* c2_w,
    float* W1, float* b1c, float* W2, float* b2c, float2* wpk2)
{
    __shared__ __align__(16) float l2T[500 * 12];
    int bx = blockIdx.x, tid = threadIdx.x;
    if (bx < 34) {
        combine_part(l1c1_w, l1c1_b, l2c1_w, l2c1_b, d1_w, d1_b, K1, KP1P, W1, b1c, bx, l2T);
    } else if (bx < 40) {
        combine_part(l1c2_w, l1c2_b, l2c2_w, l2c2_b, d2_w, d2_b, K2, KP2P, W2, b2c, bx - 34, l2T);
    } else {
        int i = (bx - 40) * 256 + tid;
        if (i < 22500) {
            int oc = i / 450, r = i - oc * 450;
            int ic = r / 9, k = r - ic * 9;
            float v = c2_w[i];
            wpk2[ic * 500 + oc * 10 + k] = make_float2(v, v);   // pad k=9 stays zero
        }
    }
}

// ---------------- conv1: register patch + packed f32x2 ----------------------
__global__ __launch_bounds__(192) void conv1_kernel(
    const float* __restrict__ x, const float* __restrict__ w,
    const float* __restrict__ bias, float* __restrict__ h1)
{
    int b = blockIdx.x;
    __shared__ __align__(16) float xs[784];
    __shared__ __align__(16) float2 ws[450];
    __shared__ __align__(16) float bs[50];
    int tid = threadIdx.x;
    {
        const float4* xb = (const float4*)(x + (size_t)b * 784);
        for (int i = tid; i < 196; i += 192) ((float4*)xs)[i] = xb[i];
        for (int i = tid; i < 450; i += 192) { float v = w[i]; ws[i] = make_float2(v, v); }
        for (int i = tid; i < 50;  i += 192) bs[i] = bias[i];
    }
    __syncthreads();
    if (tid >= 169) return;

    const int py = tid / 13, px = tid % 13;
    const int Y = 2 * py, X = 2 * px;
    float p[4][4];
    #pragma unroll
    for (int r = 0; r < 4; r++)
        #pragma unroll
        for (int c = 0; c < 4; c++) p[r][c] = xs[(Y + r) * 28 + X + c];
    unsigned long long P[4][3];
    #pragma unroll
    for (int r = 0; r < 4; r++)
        #pragma unroll
        for (int k = 0; k < 3; k++)
            asm("mov.b64 %0, {%1, %2};" : "=l"(P[r][k])
                : "r"(__float_as_uint(p[r][k])), "r"(__float_as_uint(p[r][k + 1])));

    float* hb = h1 + (size_t)b * KP1P + tid;
    for (int oc = 0; oc < 50; oc++) {
        unsigned long long aT = 0ULL, aB = 0ULL;
        #pragma unroll
        for (int ky = 0; ky < 3; ky++)
            #pragma unroll
            for (int kx = 0; kx < 3; kx++) {
                unsigned long long w2 = *(const unsigned long long*)&ws[oc * 9 + ky * 3 + kx];
                asm("fma.rn.f32x2 %0, %1, %2, %0;" : "+l"(aT) : "l"(P[ky][kx]), "l"(w2));
                asm("fma.rn.f32x2 %0, %1, %2, %0;" : "+l"(aB) : "l"(P[ky + 1][kx]), "l"(w2));
            }
        unsigned int u0, u1, u2, u3;
        asm("mov.b64 {%0, %1}, %2;" : "=r"(u0), "=r"(u1) : "l"(aT));
        asm("mov.b64 {%0, %1}, %2;" : "=r"(u2), "=r"(u3) : "l"(aB));
        float m = fmaxf(fmaxf(__uint_as_float(u0), __uint_as_float(u1)),
                        fmaxf(__uint_as_float(u2), __uint_as_float(u3)));
        m += bs[oc];
        hb[oc * 169] = fmaxf(m, 0.f);
    }
}

// ====== stagehead (stage 1): direct-LDG streamer, no smem, no barriers ======
// warp = 2 samples; block = 8 warps = 16 samples; grid (256, 2 splits)
__global__ __launch_bounds__(256) void stagehead_part_kernel(
    const float* __restrict__ f, int Kp,
    const float* __restrict__ W12, float* __restrict__ part)
{
    const int tid = threadIdx.x, lane = tid & 31, wid = tid >> 5;
    const int b0 = blockIdx.x * 16;
    const int split = blockIdx.y;
    const int s0 = b0 + wid * 2, s1 = s0 + 1;
    const int half = Kp >> 1;                 // 4352, mult of 128
    const int kBeg = split * half;
    const int kEnd = kBeg + half;

    float acc0[12], acc1[12];
    #pragma unroll
    for (int j = 0; j < 12; j++) { acc0[j] = 0.f; acc1[j] = 0.f; }

    const float* f0p = f + (size_t)s0 * Kp;
    const float* f1p = f + (size_t)s1 * Kp;

    #pragma unroll 2
    for (int k = kBeg + lane * 4; k < kEnd; k += 128) {
        float4 a0 = *(const float4*)(f0p + k);
        float4 a1 = *(const float4*)(f1p + k);
        #pragma unroll
        for (int j = 0; j < 12; j++) {
            float4 w = __ldg((const float4*)&W12[(size_t)j * Kp + k]);
            acc0[j] = fmaf(a0.x, w.x, fmaf(a0.y, w.y, fmaf(a0.z, w.z, fmaf(a0.w, w.w, acc0[j]))));
            acc1[j] = fmaf(a1.x, w.x, fmaf(a1.y, w.y, fmaf(a1.z, w.z, fmaf(a1.w, w.w, acc1[j]))));
        }
    }

    #pragma unroll
    for (int j = 0; j < 12; j++) {
        #pragma unroll
        for (int off = 16; off; off >>= 1) {
            acc0[j] += __shfl_xor_sync(0xffffffffu, acc0[j], off);
            acc1[j] += __shfl_xor_sync(0xffffffffu, acc1[j], off);
        }
    }
    if (lane == 0) {
        #pragma unroll
        for (int j = 0; j < 12; j++) {
            part[s0 * 24 + split * 12 + j] = acc0[j];
            part[s1 * 24 + split * 12 + j] = acc1[j];
        }
    }
}

// ---------------- conv2 + fused stage-2 head --------------------------------
// dyn smem: hs[50][13][14] @0 | wb[2][2500]f2 @36416 | bss @76416 | red @76624
#define C2_SMEM 77056
__global__ __launch_bounds__(256, 2) void conv2_kernel(
    const float* __restrict__ h1, const float2* __restrict__ wpk,
    const float* __restrict__ bias, float* __restrict__ h2,
    const float* __restrict__ part, const float* __restrict__ b1c,
    const float* __restrict__ W2, const float* __restrict__ b2c,
    int* __restrict__ e1, int* __restrict__ e2, float* __restrict__ o2)
{
    extern __shared__ __align__(16) char csm[];
    float*  hs  = (float*)csm;                       // padded rows of 14
    float2* wb  = (float2*)(csm + 36416);            // [2][2500]
    float*  bss = (float*)(csm + 76416);             // [50]
    float*  red = (float*)(csm + 76624);             // [12][8] + [12]
    __shared__ int sflag;

    const int b = blockIdx.x;
    const int tid = threadIdx.x;
    if (tid == 0) {
        float m0 = part[b * 24 + 10] + part[b * 24 + 22] + __ldg(&b1c[10]);
        float m1 = part[b * 24 + 11] + part[b * 24 + 23] + __ldg(&b1c[11]);
        int fl = (m0 >= m1) ? 1 : 0;
        e1[b] = fl;
        sflag = fl;
        if (fl) e2[b] = 0;     // deterministic; value unused for e1 samples
    }
    __syncthreads();
    if (sflag) return;

    {
        const float* hb = h1 + (size_t)b * KP1P;
        for (int i = tid; i < 8450; i += 256) {
            int ic = i / 169, rem = i - ic * 169;
            int r = rem / 13, c = rem - r * 13;
            hs[ic * 182 + r * 14 + c] = hb[i];
        }
        for (int i = tid; i < 50; i += 256) bss[i] = bias[i];
        for (int i = tid; i < 1250; i += 256)
            ((float4*)wb)[i] = ((const float4*)wpk)[i];
    }
    __syncthreads();

    const int osub = tid / 25, pos = tid % 25;
    const int oc0 = osub * 5;
    const int py = pos / 5, px = pos % 5;
    const int Y = 2 * py, X = 2 * px;
    const bool active = (tid < 250);

    unsigned long long aT[5], aB[5];
    #pragma unroll
    for (int j = 0; j < 5; j++) { aT[j] = 0ULL; aB[j] = 0ULL; }

    for (int t = 0; t < 10; t++) {
        const int cur = t & 1;
        if (t + 1 < 10) {
            const float4* src = (const float4*)wpk + (t + 1) * 1250;
            float4* dst = (float4*)(wb + (cur ^ 1) * 2500);
            for (int i = tid; i < 1250; i += 256) dst[i] = src[i];
        }
        if (active) {
            #pragma unroll
            for (int i5 = 0; i5 < 5; i5++) {
                const float* hc = hs + (t * 5 + i5) * 182;
                unsigned long long P[4][3];
                #pragma unroll
                for (int r = 0; r < 4; r++) {
                    float2 v0 = *(const float2*)(hc + (Y + r) * 14 + X);
                    float2 v1 = *(const float2*)(hc + (Y + r) * 14 + X + 2);
                    asm("mov.b64 %0, {%1, %2};" : "=l"(P[r][0])
                        : "r"(__float_as_uint(v0.x)), "r"(__float_as_uint(v0.y)));
                    asm("mov.b64 %0, {%1, %2};" : "=l"(P[r][1])
                        : "r"(__float_as_uint(v0.y)), "r"(__float_as_uint(v1.x)));
                    asm("mov.b64 %0, {%1, %2};" : "=l"(P[r][2])
                        : "r"(__float_as_uint(v1.x)), "r"(__float_as_uint(v1.y)));
                }
                const float2* wrow = wb + cur * 2500 + (i5 * 50 + oc0) * 10;
                #pragma unroll
                for (int j = 0; j < 5; j++) {
                    const float2* wp = wrow + j * 10;
                    ulonglong2 q0 = *(const ulonglong2*)(wp);
                    ulonglong2 q1 = *(const ulonglong2*)(wp + 2);
                    ulonglong2 q2 = *(const ulonglong2*)(wp + 4);
                    ulonglong2 q3 = *(const ulonglong2*)(wp + 6);
                    unsigned long long w8 = *(const unsigned long long*)(wp + 8);
                    unsigned long long wv[9] = {q0.x, q0.y, q1.x, q1.y,
                                                q2.x, q2.y, q3.x, q3.y, w8};
                    #pragma unroll
                    for (int ky = 0; ky < 3; ky++)
                        #pragma unroll
                        for (int kx = 0; kx < 3; kx++) {
                            asm("fma.rn.f32x2 %0, %1, %2, %0;"
                                : "+l"(aT[j]) : "l"(P[ky][kx]), "l"(wv[ky * 3 + kx]));
                            asm("fma.rn.f32x2 %0, %1, %2, %0;"
                                : "+l"(aB[j]) : "l"(P[ky + 1][kx]), "l"(wv[ky * 3 + kx]));
                        }
                }
            }
        }
        __syncthreads();
    }

    // finalize conv outputs + per-thread head partials
    float hd[12];
    #pragma unroll
    for (int jj = 0; jj < 12; jj++) hd[jj] = 0.f;
    if (active) {
        float v5[5];
        #pragma unroll
        for (int j = 0; j < 5; j++) {
            unsigned int u0, u1, u2, u3;
            asm("mov.b64 {%0, %1}, %2;" : "=r"(u0), "=r"(u1) : "l"(aT[j]));
            asm("mov.b64 {%0, %1}, %2;" : "=r"(u2), "=r"(u3) : "l"(aB[j]));
            float m = fmaxf(fmaxf(__uint_as_float(u0), __uint_as_float(u1)),
                            fmaxf(__uint_as_float(u2), __uint_as_float(u3)));
            m += bss[oc0 + j];
            v5[j] = fmaxf(m, 0.f);
            h2[(size_t)b * KP2P + (oc0 + j) * 25 + pos] = v5[j];
        }
        #pragma unroll
        for (int jj = 0; jj < 12; jj++) {
            float s = 0.f;
            #pragma unroll
            for (int j = 0; j < 5; j++)
                s += v5[j] * __ldg(&W2[(size_t)jj * KP2P + (oc0 + j) * 25 + pos]);
            hd[jj] = s;
        }
    }
    // block reduce 12 sums
    const int lane = tid & 31, wrp = tid >> 5;
    #pragma unroll
    for (int jj = 0; jj < 12; jj++) {
        #pragma unroll
        for (int off = 16; off; off >>= 1)
            hd[jj] += __shfl_xor_sync(0xffffffffu, hd[jj], off);
    }
    if (lane == 0) {
        #pragma unroll
        for (int jj = 0; jj < 12; jj++) red[jj * 8 + wrp] = hd[jj];
    }
    __syncthreads();
    if (tid < 12) {
        float s = __ldg(&b2c[tid]);
        #pragma unroll
        for (int w = 0; w < 8; w++) s += red[tid * 8 + w];
        red[96 + tid] = s;
    }
    __syncthreads();
    if (tid == 0) e2[b] = (red[96 + 10] >= red[96 + 11]) ? 1 : 0;
    if (tid < 10) o2[b * 10 + tid] = red[96 + tid];
}

// ---------------- conv3 (skips samples exiting at 1 or 2) -------------------
__global__ void conv3_kernel(const float* __restrict__ h2,
                             const float* __restrict__ w,
                             const float* __restrict__ bias,
                             float* __restrict__ f3,
                             const int* __restrict__ e1,
                             const int* __restrict__ e2)
{
    int b = blockIdx.x;
    if (e1[b] || e2[b]) return;
    __shared__ __align__(16) float hs[1250];
    const float* hb = h2 + (size_t)b * KP2P;
    for (int i = threadIdx.x; i < 1250; i += blockDim.x) hs[i] = hb[i];
    __syncthreads();

    int oc = threadIdx.x;
    if (oc >= 50) return;
    float a0 = 0.f, a1 = 0.f, a2 = 0.f, a3 = 0.f;
    for (int ic = 0; ic < 50; ic++) {
        const float* hc = hs + ic * 25;
        #pragma unroll
        for (int ky = 0; ky < 3; ky++)
            #pragma unroll
            for (int kx = 0; kx < 3; kx++) {
                float wv = __ldg(&w[oc * 450 + ic * 9 + ky * 3 + kx]);
                a0 += hc[ky * 5 + kx] * wv;
                a1 += hc[ky * 5 + kx + 1] * wv;
                a2 += hc[(ky + 1) * 5 + kx] * wv;
                a3 += hc[(ky + 1) * 5 + kx + 1] * wv;
            }
    }
    float m = fmaxf(fmaxf(a0, a1), fmaxf(a2, a3)) + __ldg(&bias[oc]);
    f3[b * 50 + oc] = fmaxf(m, 0.f);
}

// ==== stage3 + final fused ===================================================
#define S3_G 32
#define S3_SMEM ((25000 + 5000 + 500 + S3_G * 50 + S3_G * 500 + S3_G * 10) * 4)

__global__ __launch_bounds__(256) void stage3final_kernel(
    const float* __restrict__ f3,
    const float* __restrict__ l1w, const float* __restrict__ l1b,
    const float* __restrict__ l2w, const float* __restrict__ l2b,
    const int* __restrict__ e1, const int* __restrict__ e2,
    const float* __restrict__ part, const float* __restrict__ b1c,
    const float* __restrict__ o2, float* __restrict__ out)
{
    extern __shared__ __align__(16) float sm[];
    float* w1  = sm;
    float* w2  = sm + 25000;
    float* b1  = sm + 30000;
    float* fs  = sm + 30500;
    float* hid = sm + 32100;
    float* o3s = sm + 48100;
    int tid = threadIdx.x;
    int b0 = blockIdx.x * S3_G;

    for (int i = tid; i < 25000; i += 256) w1[i] = l1w[i];
    for (int i = tid; i < 5000;  i += 256) w2[i] = l2w[i];
    for (int i = tid; i < 500;   i += 256) b1[i] = l1b[i];
    for (int i = tid; i < S3_G * 50; i += 256) fs[i] = f3[b0 * 50 + i];
    __syncthreads();

    for (int hh = tid; hh < S3_G * 500; hh += 256) {
        int s = hh / 500, j = hh - s * 500;
        float a = b1[j];
        const float* fr = fs + s * 50;
        const float* wr = w1 + j * 50;
        #pragma unroll 10
        for (int k = 0; k < 50; k++) a += fr[k] * wr[k];
        hid[hh] = fmaxf(a, 0.f);
    }
    __syncthreads();

    for (int oo = tid; oo < S3_G * 10; oo += 256) {
        int s = oo / 10, n = oo - s * 10;
        float a = __ldg(&l2b[n]);
        const float* hr = hid + s * 500;
        const float* wr = w2 + n * 500;
        #pragma unroll 4
        for (int j = 0; j < 500; j++) a += hr[j] * wr[j];
        o3s[s * 10 + n] = a;
    }
    __syncthreads();

    if (tid < S3_G) {
        int b = b0 + tid;
        float v[10];
        if (e1[b]) {
            #pragma unroll
            for (int j = 0; j < 10; j++)
                v[j] = part[b * 24 + j] + part[b * 24 + 12 + j] + __ldg(&b1c[j]);
        } else if (e2[b]) {
            #pragma unroll
            for (int j = 0; j < 10; j++) v[j] = o2[b * 10 + j];
        } else {
            #pragma unroll
            for (int j = 0; j < 10; j++) v[j] = o3s[tid * 10 + j];
        }
        float mx = -1e30f;
        #pragma unroll
        for (int j = 0; j < 10; j++) mx = fmaxf(mx, v[j]);
        float sum = 0.f;
        #pragma unroll
        for (int j = 0; j < 10; j++) sum += expf(v[j] - mx);
        float l = logf(sum);
        #pragma unroll
        for (int j = 0; j < 10; j++) out[b * 10 + j] = v[j] - mx - l;
    }
}

// ---------------- launch ----------------------------------------------------
extern "C" void kernel_launch(void* const* d_in, const int* in_sizes, int n_in,
                              void* d_out, int out_size)
{
    const float* x      = (const float*)d_in[0];
    const float* c1_w   = (const float*)d_in[1];
    const float* c1_b   = (const float*)d_in[2];
    const float* c2_w   = (const float*)d_in[3];
    const float* c2_b   = (const float*)d_in[4];
    const float* c3_w   = (const float*)d_in[5];
    const float* c3_b   = (const float*)d_in[6];
    const float* l1c1_w = (const float*)d_in[7];
    const float* l1c1_b = (const float*)d_in[8];
    const float* l2c1_w = (const float*)d_in[9];
    const float* l2c1_b = (const float*)d_in[10];
    const float* l1c2_w = (const float*)d_in[11];
    const float* l1c2_b = (const float*)d_in[12];
    const float* l2c2_w = (const float*)d_in[13];
    const float* l2c2_b = (const float*)d_in[14];
    const float* l1_w   = (const float*)d_in[15];
    const float* l1_b   = (const float*)d_in[16];
    const float* l2_w   = (const float*)d_in[17];
    const float* l2_b   = (const float*)d_in[18];
    const float* d1_w   = (const float*)d_in[19];
    const float* d1_b   = (const float*)d_in[20];
    const float* d2_w   = (const float*)d_in[21];
    const float* d2_b   = (const float*)d_in[22];
    float* out = (float*)d_out;

    float *h1, *h2, *f3, *o2, *W1, *W2, *b1c, *b2c, *part1;
    float2 *wpk2;
    int *e1, *e2;
    cudaGetSymbolAddress((void**)&h1,   g_h1);
    cudaGetSymbolAddress((void**)&h2,   g_h2);
    cudaGetSymbolAddress((void**)&f3,   g_f3);
    cudaGetSymbolAddress((void**)&o2,   g_o2);
    cudaGetSymbolAddress((void**)&e1,   g_e1);
    cudaGetSymbolAddress((void**)&e2,   g_e2);
    cudaGetSymbolAddress((void**)&W1,   g_W1);
    cudaGetSymbolAddress((void**)&W2,   g_W2);
    cudaGetSymbolAddress((void**)&b1c,  g_b1c);
    cudaGetSymbolAddress((void**)&b2c,  g_b2c);
    cudaGetSymbolAddress((void**)&part1, g_part1);
    cudaGetSymbolAddress((void**)&wpk2, g_wpk2);

    static cudaStream_t s2 = nullptr;
    static cudaEvent_t evA = nullptr, evB = nullptr;
    static int attr_set = 0;
    if (!attr_set) {
        cudaFuncSetAttribute(conv2_kernel,
                             cudaFuncAttributeMaxDynamicSharedMemorySize, C2_SMEM);
        cudaFuncSetAttribute(stage3final_kernel,
                             cudaFuncAttributeMaxDynamicSharedMemorySize, S3_SMEM);
        cudaStreamCreateWithFlags(&s2, cudaStreamNonBlocking);
        cudaEventCreateWithFlags(&evA, cudaEventDisableTiming);
        cudaEventCreateWithFlags(&evB, cudaEventDisableTiming);
        attr_set = 1;
    }

    // fork: prep on side stream, conv1 on main stream (independent)
    cudaEventRecord(evA, 0);
    cudaStreamWaitEvent(s2, evA, 0);
    prep_kernel<<<128, 256, 0, s2>>>(l1c1_w, l1c1_b, l2c1_w, l2c1_b,
                                     l1c2_w, l1c2_b, l2c2_w, l2c2_b,
                                     d1_w, d1_b, d2_w, d2_b, c2_w,
                                     W1, b1c, W2, b2c, wpk2);
    cudaEventRecord(evB, s2);

    conv1_kernel<<<BATCH, 192>>>(x, c1_w, c1_b, h1);

    // join: sh1 needs W1 (prep) + h1 (conv1)
    cudaStreamWaitEvent(0, evB, 0);
    stagehead_part_kernel<<<dim3(BATCH / 16, 2), 256>>>(h1, KP1P, W1, part1);

    // stage 2: conv2 derives e1, computes h2, and fused head -> o2/e2
    conv2_kernel<<<BATCH, 256, C2_SMEM>>>(h1, wpk2, c2_b, h2, part1, b1c,
                                          W2, b2c, e1, e2, o2);

    // stage 3 + final select/log_softmax
    conv3_kernel<<<BATCH, 64>>>(h2, c3_w, c3_b, f3, e1, e2);
    stage3final_kernel<<<BATCH / S3_G, 256, S3_SMEM>>>(
        f3, l1_w, l1_b, l2_w, l2_b, e1, e2, part1, b1c, o2, out);
}